// round 4
// baseline (speedup 1.0000x reference)
#include <cuda_runtime.h>
#include <math.h>

#define Bn   4
#define CIN  256
#define CE   64
#define Gn   4
#define Hn   80
#define Wn   80
#define Nn   (Hn*Wn)        // 6400
#define ROW  260            // G * 65
#define EPSV 1e-8f
#define BND  8              // max levels per band
#define BCAP 1024           // max nodes per band (= 256 threads * quota 4)

// ---------------- static device scratch ----------------
__device__ float g_ft   [Bn*Nn*CIN];
__device__ float g_embt [Bn*Nn*CE];
__device__ float g_gembt[Bn*Nn*CE];
__device__ float g_conf [Bn*Nn*Gn];
__device__ float g_w    [Bn*Gn*Nn];
__device__ float g_cA   [Bn*Nn*ROW];
__device__ float g_cB   [Bn*Nn*ROW];
__device__ float g_m0   [Bn*Nn*4];
__device__ float g_m1   [Bn*Nn*4];
__device__ int   g_anc0 [Bn*Nn];
__device__ int   g_anc1 [Bn*Nn];
__device__ int   g_inv  [Bn*Nn];
__device__ int   g_ls   [Bn*(Nn+2)];
__device__ int   g_nlvl [Bn];
// band machinery for up-sweep
__device__ int           g_janc [Bn*BND*Nn];      // d-step ancestor, d=1..8
__device__ float         g_jm   [Bn*Gn*BND*Nn];   // d-step multiplier
__device__ unsigned char g_rd   [Bn*Nn];          // band-relative depth (1..8)
__device__ int           g_bstart[Bn*(Nn+1)];     // band node-start offsets
__device__ int           g_nband [Bn];

// ---------------- packed f32x2 FMA ----------------
__device__ __forceinline__ void ffma2(unsigned long long &d,
                                      unsigned long long a,
                                      unsigned long long b) {
    asm("fma.rn.f32x2 %0, %1, %2, %0;" : "+l"(d) : "l"(a), "l"(b));
}

// ---------------- K0: transpose feature (b,c,n) -> (b,n,c) ----------------
__global__ void k_transpose(const float* __restrict__ f) {
    __shared__ float t[32][33];
    int b = blockIdx.z, c0 = blockIdx.y * 32, n0 = blockIdx.x * 32;
    int tx = threadIdx.x, ty = threadIdx.y;
    const float* src = f + ((size_t)b * CIN + c0) * Nn + n0;
#pragma unroll
    for (int r = 0; r < 32; r += 8)
        t[ty + r][tx] = src[(size_t)(ty + r) * Nn + tx];
    __syncthreads();
    float* dst = g_ft + ((size_t)b * Nn + n0) * CIN + c0;
#pragma unroll
    for (int r = 0; r < 32; r += 8)
        dst[(size_t)(ty + r) * CIN + tx] = t[tx][ty + r];
}

// ---------------- K1: levels + inverse perm + band construction ----------------
__global__ __launch_bounds__(256) void k_levels(const int* __restrict__ order,
                                                const int* __restrict__ parent) {
    extern __shared__ int sh[];
    int* a0 = sh;
    int* a1 = sh + Nn;
    int* l0 = sh + 2 * Nn;
    int* l1 = sh + 3 * Nn;
    __shared__ int s_more, s_nb;
    int b = blockIdx.x, tid = threadIdx.x;
    const int* pp = parent + b * Nn;
    const int* od = order + b * Nn;
    for (int k = tid; k < Nn; k += blockDim.x) {
        a0[k] = pp[k];
        l0[k] = (k == 0) ? 0 : 1;
        g_inv[b * Nn + od[k]] = k;
    }
    __syncthreads();
    int* aa = a0; int* ab = a1; int* la = l0; int* lb = l1;
    for (int it = 0; it < 13; ++it) {
        if (tid == 0) s_more = 0;
        __syncthreads();
        int any = 0;
        for (int k = tid; k < Nn; k += blockDim.x) {
            int a = aa[k];
            lb[k] = la[k] + la[a];
            int na = aa[a];
            ab[k] = na;
            any |= na;
        }
        if (any) s_more = 1;
        __syncthreads();
        int* tmp = aa; aa = ab; ab = tmp;
        tmp = la; la = lb; lb = tmp;
        if (!s_more) break;
    }
    // level starts: write to global AND into ab (smem ls)
    int* ls = g_ls + b * (Nn + 2);
    for (int k = tid; k < Nn; k += blockDim.x) {
        if (k == 0) { ls[0] = 0; ab[0] = 0; }
        else if (la[k] != la[k - 1]) { ls[la[k]] = k; ab[la[k]] = k; }
        if (k == Nn - 1) { g_nlvl[b] = la[k] + 1; ls[la[k] + 1] = Nn; }
    }
    __syncthreads();
    // band build (thread 0, greedy): lb = band starts, aa = band top level
    if (tid == 0) {
        int nlvl = la[Nn - 1] + 1;
        ab[nlvl] = Nn;
        int nb = 0;
        int lev = 1;
        while (lev < nlvl) {
            int lstart = ab[lev], lend = ab[lev + 1];
            int csz = lend - lstart;
            if (csz > BCAP) {
                int s2 = lstart;
                while (s2 < lend) {
                    int e2 = s2 + BCAP; if (e2 > lend) e2 = lend;
                    lb[nb] = s2; aa[nb] = lev; nb++;
                    s2 = e2;
                }
                lev++;
            } else {
                int nlv = 1, cnt = csz;
                while (lev + nlv < nlvl && nlv < BND) {
                    int add = ab[lev + nlv + 1] - ab[lev + nlv];
                    if (cnt + add > BCAP) break;
                    cnt += add; nlv++;
                }
                lb[nb] = lstart; aa[nb] = lev; nb++;
                lev += nlv;
            }
        }
        lb[nb] = Nn;
        s_nb = nb;
        g_nband[b] = nb;
    }
    __syncthreads();
    int nb = s_nb;
    for (int i = tid; i <= nb; i += 256) g_bstart[b * (Nn + 1) + i] = lb[i];
    for (int i = 0; i < nb; ++i) {
        int s2 = lb[i], e2 = lb[i + 1], tl = aa[i];
        for (int k = s2 + tid; k < e2; k += 256)
            g_rd[b * Nn + k] = (unsigned char)(la[k] - tl + 1);
    }
}

// ---------------- K2: skinny GEMMs via packed f32x2 FMA ----------------
__global__ __launch_bounds__(256) void k_gemm(const float* __restrict__ feat,
                                              const float* __restrict__ guide,
                                              const float* __restrict__ We,
                                              const float* __restrict__ Wc,
                                              const float* __restrict__ Wg) {
    __shared__ char smraw[34816];
    float*  xs = reinterpret_cast<float*>(smraw);
    float2* ws = reinterpret_cast<float2*>(smraw + 16384);
    float*  stage = reinterpret_cast<float*>(smraw);

    int tid = threadIdx.x;
    int os = tid >> 5;
    int nq = tid & 31;
    int n0 = blockIdx.x * 128;
    int b  = blockIdx.y;
    int path = blockIdx.z;

    const float* X = (path == 0 ? feat : guide) + (size_t)b * CIN * Nn;

    unsigned long long acc[9][2];
#pragma unroll
    for (int j = 0; j < 9; ++j) { acc[j][0] = 0ull; acc[j][1] = 0ull; }

    for (int kc = 0; kc < 256; kc += 32) {
        const float* Xb = X + (size_t)kc * Nn + n0;
#pragma unroll
        for (int i = tid; i < 1024; i += 256) {
            int kk = i >> 5, c4 = i & 31;
            *reinterpret_cast<float4*>(&xs[kk * 128 + c4 * 4]) =
                *reinterpret_cast<const float4*>(&Xb[(size_t)kk * Nn + c4 * 4]);
        }
#pragma unroll
        for (int i = tid; i < 2304; i += 256) {
            int o = i >> 5, kk = i & 31;
            float v = 0.f;
            if (path == 0) {
                if (o < 64)       v = We[o * 256 + kc + kk];
                else if (o < 68)  v = Wc[(o - 64) * 256 + kc + kk];
            } else {
                if (o < 64)       v = Wg[o * 256 + kc + kk];
            }
            ws[i] = make_float2(v, v);
        }
        __syncthreads();
#pragma unroll 2
        for (int kk = 0; kk < 32; ++kk) {
            float4 x4 = *reinterpret_cast<const float4*>(&xs[kk * 128 + nq * 4]);
            unsigned long long xlo = *reinterpret_cast<unsigned long long*>(&x4.x);
            unsigned long long xhi = *reinterpret_cast<unsigned long long*>(&x4.z);
#pragma unroll
            for (int j = 0; j < 9; ++j) {
                float2 wv = ws[(os * 9 + j) * 32 + kk];
                unsigned long long wp = *reinterpret_cast<unsigned long long*>(&wv);
                ffma2(acc[j][0], xlo, wp);
                ffma2(acc[j][1], xhi, wp);
            }
        }
        __syncthreads();
    }
#pragma unroll
    for (int j = 0; j < 9; ++j) {
        int o = os * 9 + j;
        if (o < 68) {
            float2 lo = *reinterpret_cast<float2*>(&acc[j][0]);
            float2 hi = *reinterpret_cast<float2*>(&acc[j][1]);
            stage[(nq * 4 + 0) * 68 + o] = lo.x;
            stage[(nq * 4 + 1) * 68 + o] = lo.y;
            stage[(nq * 4 + 2) * 68 + o] = hi.x;
            stage[(nq * 4 + 3) * 68 + o] = hi.y;
        }
    }
    __syncthreads();
    float* outt = (path == 0) ? g_embt : g_gembt;
#pragma unroll
    for (int i = tid; i < 2048; i += 256) {
        int n = i >> 4, c4 = i & 15;
        float4 v = *reinterpret_cast<float4*>(&stage[n * 68 + c4 * 4]);
        *reinterpret_cast<float4*>(&outt[((size_t)b * Nn + n0 + n) * 64 + c4 * 4]) = v;
    }
    if (path == 0) {
#pragma unroll
        for (int i = tid; i < 512; i += 256) {
            int n = i >> 2, gg = i & 3;
            float x = stage[n * 68 + 64 + gg];
            g_conf[((size_t)b * Nn + n0 + n) * 4 + gg] = 1.f / (1.f + expf(-x));
        }
    }
}

// ---------------- K3: edge weights, 2 threads per node ----------------
__global__ __launch_bounds__(256) void k_w(const int* __restrict__ order,
                                           const int* __restrict__ parent,
                                           const float* __restrict__ beta) {
    int b = blockIdx.y;
    int idx = blockIdx.x * 256 + threadIdx.x;
    int k = idx >> 1, half = idx & 1;
    if (k >= Nn) return;
    int n1 = order[b * Nn + k];
    int p  = parent[b * Nn + k];
    int n0 = order[b * Nn + p];
    int coff = half * 32;
    const float4* e1 = reinterpret_cast<const float4*>(g_embt  + ((size_t)b * Nn + n1) * 64 + coff);
    const float4* e0 = reinterpret_cast<const float4*>(g_embt  + ((size_t)b * Nn + n0) * 64 + coff);
    const float4* q1 = reinterpret_cast<const float4*>(g_gembt + ((size_t)b * Nn + n1) * 64 + coff);
    const float4* q0 = reinterpret_cast<const float4*>(g_gembt + ((size_t)b * Nn + n0) * 64 + coff);
    float d[2] = {0.f, 0.f};
#pragma unroll
    for (int i = 0; i < 8; ++i) {
        float4 a = e1[i], c = e0[i];
        float dx = a.x - c.x, dy = a.y - c.y, dz = a.z - c.z, dw = a.w - c.w;
        d[i >> 2] += dx * dx + dy * dy + dz * dz + dw * dw;
    }
#pragma unroll
    for (int i = 0; i < 8; ++i) {
        float4 a = q1[i], c = q0[i];
        float dx = a.x - c.x, dy = a.y - c.y, dz = a.z - c.z, dw = a.w - c.w;
        d[i >> 2] += dx * dx + dy * dy + dz * dz + dw * dw;
    }
#pragma unroll
    for (int j = 0; j < 2; ++j) {
        int g = half * 2 + j;
        float bb = beta[g];
        g_w[((size_t)b * 4 + g) * Nn + k] = expf(-(d[j] + bb * bb));
    }
}

// ---------------- K3b: per-distance jump tables (anc_d, m_d), d=1..8 ----------------
__global__ __launch_bounds__(1024) void k_jump(const int* __restrict__ parent) {
    int b = blockIdx.x, tid = threadIdx.x;
    const int* pp = parent + b * Nn;
    int* janc = g_janc + (size_t)b * BND * Nn;
    for (int k = tid; k < Nn; k += 1024) {
        int p = (k == 0) ? 0 : pp[k];
        janc[k] = p;
#pragma unroll
        for (int g = 0; g < 4; ++g)
            g_jm[(((size_t)(b * 4 + g)) * BND) * Nn + k] =
                (k == 0) ? 0.f : g_w[((size_t)b * 4 + g) * Nn + k];
    }
    __syncthreads();
    for (int d = 1; d < BND; ++d) {
        for (int k = tid; k < Nn; k += 1024) {
            int ap = janc[(d - 1) * Nn + k];
            janc[d * Nn + k] = janc[ap];          // anc_1[ap]
#pragma unroll
            for (int g = 0; g < 4; ++g) {
                const float* jm = g_jm + ((size_t)(b * 4 + g)) * BND * Nn;
                float v = jm[(d - 1) * Nn + k] * jm[ap];
                g_jm[((size_t)(b * 4 + g)) * BND * Nn + d * Nn + k] = v;
            }
        }
        __syncthreads();
    }
}

// ---------------- K4a: banded up-sweep core ----------------
template<int CH>
__device__ __forceinline__ void up_band_core(float* sagg, int b, int g, int tid, int nb) {
    const int* bst = g_bstart + b * (Nn + 1);
    const unsigned char* rd = g_rd + b * Nn;
    const int* janc = g_janc + (size_t)b * BND * Nn;
    const float* jm = g_jm + ((size_t)(b * 4 + g)) * BND * Nn;

    if (nb <= 0) return;
    int e = Nn;
    int s = __ldg(&bst[nb - 1]);
    for (int i = nb - 1; i >= 0; --i) {
        int s_pf = (i > 0) ? __ldg(&bst[i - 1]) : 0;
        float v[4][CH]; int kn[4]; int rr[4];
#pragma unroll
        for (int q = 0; q < 4; ++q) {
            int k = s + tid + 256 * q;
            kn[q] = k;
            if (k < e) {
                rr[q] = rd[k];
                if (CH == 8) {
                    float4 a  = *reinterpret_cast<const float4*>(&sagg[k * 8]);
                    float4 bb = *reinterpret_cast<const float4*>(&sagg[k * 8 + 4]);
                    v[q][0] = a.x;  v[q][1] = a.y;  v[q][2] = a.z;  v[q][3] = a.w;
                    v[q][4] = bb.x; v[q][5] = bb.y; v[q][6] = bb.z; v[q][7] = bb.w;
                } else {
                    v[q][0] = sagg[k];
                }
            }
        }
        __syncthreads();
#pragma unroll
        for (int q = 0; q < 4; ++q) {
            int k = kn[q];
            if (k < e) {
                int r = rr[q];
                for (int d = 0; d < r; ++d) {
                    int a = __ldg(&janc[d * Nn + k]);
                    float mv = __ldg(&jm[d * Nn + k]);
#pragma unroll
                    for (int c = 0; c < CH; ++c)
                        atomicAdd(&sagg[a * CH + c], mv * v[q][c]);
                }
            }
        }
        __syncthreads();
        e = s; s = s_pf;
    }
}

__global__ __launch_bounds__(256, 1) void k_up(const int* __restrict__ order,
                                               const int* __restrict__ parent) {
    extern __shared__ float sagg[];
    __shared__ int s_nb;
    int ci = blockIdx.x, g = blockIdx.y, b = blockIdx.z;
    int c0 = ci * 8;
    int tid = threadIdx.x;
    const int* od = order + b * Nn;
    const float* gw = g_w + ((size_t)b * 4 + g) * Nn;

    if (tid == 0) s_nb = g_nband[b];

    if (ci < 8) {
        for (int k = tid; k < Nn; k += 256) {
            int n = od[k];
            float cf = g_conf[((size_t)b * Nn + n) * 4 + g];
            const float4* f4 = reinterpret_cast<const float4*>(
                g_ft + ((size_t)b * Nn + n) * CIN + g * 64 + c0);
            float4 v0 = f4[0], v1 = f4[1];
            float* dst = &sagg[k * 8];
            dst[0] = v0.x * cf; dst[1] = v0.y * cf; dst[2] = v0.z * cf; dst[3] = v0.w * cf;
            dst[4] = v1.x * cf; dst[5] = v1.y * cf; dst[6] = v1.z * cf; dst[7] = v1.w * cf;
        }
        __syncthreads();
        up_band_core<8>(sagg, b, g, tid, s_nb);
        for (int k = tid; k < Nn; k += 256) {
            float w = (k == 0) ? 0.f : gw[k];
            float f = (k == 0) ? 1.f : (1.f - w * w);
            float* dst = g_cA + ((size_t)b * Nn + k) * ROW + g * 65 + c0;
#pragma unroll
            for (int c = 0; c < 8; ++c) dst[c] = f * sagg[k * 8 + c];
        }
    } else {
        for (int k = tid; k < Nn; k += 256) {
            int n = od[k];
            sagg[k] = g_conf[((size_t)b * Nn + n) * 4 + g];
        }
        __syncthreads();
        up_band_core<1>(sagg, b, g, tid, s_nb);
        for (int k = tid; k < Nn; k += 256) {
            float w = (k == 0) ? 0.f : gw[k];
            float f = (k == 0) ? 1.f : (1.f - w * w);
            g_cA[((size_t)b * Nn + k) * ROW + g * 65 + 64] = f * sagg[k];
        }
    }
}

// ---------------- K4b: affine jump doubling (global, throughput) ----------------
template<int FIRST>
__global__ __launch_bounds__(256) void k_double(const float* __restrict__ c_in,
                                                float* __restrict__ c_out,
                                                const float* __restrict__ m_in,
                                                float* __restrict__ m_out,
                                                const int* __restrict__ anc_in,
                                                int* __restrict__ anc_out,
                                                const int* __restrict__ parent) {
    int b = blockIdx.y;
    int k = blockIdx.x * 2 + (threadIdx.x >> 7);
    int t = threadIdx.x & 127;
    int anc = FIRST ? parent[b * Nn + k] : anc_in[b * Nn + k];
    const float* cs = c_in + ((size_t)b * Nn + k) * ROW;
    const float* ca = c_in + ((size_t)b * Nn + anc) * ROW;
    float* co = c_out + ((size_t)b * Nn + k) * ROW;
#pragma unroll
    for (int s = 0; s < 3; ++s) {
        int ch = t + 128 * s;
        if (ch < ROW) {
            int g = (ch >= 195) ? 3 : (ch >= 130) ? 2 : (ch >= 65) ? 1 : 0;
            float m;
            if (FIRST) m = (k == 0) ? 0.f : g_w[((size_t)b * 4 + g) * Nn + k];
            else       m = m_in[((size_t)b * Nn + k) * 4 + g];
            co[ch] = fmaf(m, ca[ch], cs[ch]);
        }
    }
    if (t < 4) {
        float ms, ma;
        if (FIRST) {
            ms = (k == 0) ? 0.f : g_w[((size_t)b * 4 + t) * Nn + k];
            ma = (anc == 0) ? 0.f : g_w[((size_t)b * 4 + t) * Nn + anc];
        } else {
            ms = m_in[((size_t)b * Nn + k) * 4 + t];
            ma = m_in[((size_t)b * Nn + anc) * 4 + t];
        }
        m_out[((size_t)b * Nn + k) * 4 + t] = ms * ma;
    }
    if (t == 4) {
        anc_out[b * Nn + k] = FIRST ? parent[b * Nn + anc] : anc_in[b * Nn + anc];
    }
}

// ---------------- K4c: strided down-sweep (16 levels per phase) ----------------
template<int CH>
__device__ __forceinline__ void down_core(float* sout, const float* __restrict__ cin,
                                          const float* __restrict__ mm,
                                          const int* __restrict__ aa,
                                          const int* sls16, int nph,
                                          int coloff, int g, int tid) {
    float rc[4], rm[4]; int ra[4];
    int s = sls16[0], e = sls16[1];
    {
        int cnt = (e - s) * CH;
#pragma unroll
        for (int j = 0; j < 4; ++j) {
            int i = tid + 256 * j;
            if (i < cnt) {
                int k = s + i / CH, c = i % CH;
                rc[j] = cin[(size_t)k * ROW + coloff + c];
                rm[j] = mm[(size_t)k * 4 + g];
                ra[j] = aa[k];
            }
        }
    }
    for (int t = 0; t < nph; ++t) {
        int s_c = s, e_c = e;
        float cc[4], cm[4]; int ca[4];
#pragma unroll
        for (int j = 0; j < 4; ++j) { cc[j] = rc[j]; cm[j] = rm[j]; ca[j] = ra[j]; }
        int s_n = 0, e_n = 0;
        if (t + 1 < nph) {
            s_n = sls16[t + 1]; e_n = sls16[t + 2];
            int cntn = (e_n - s_n) * CH;
#pragma unroll
            for (int j = 0; j < 4; ++j) {
                int i = tid + 256 * j;
                if (i < cntn) {
                    int k = s_n + i / CH, c = i % CH;
                    rc[j] = cin[(size_t)k * ROW + coloff + c];
                    rm[j] = mm[(size_t)k * 4 + g];
                    ra[j] = aa[k];
                }
            }
        }
        int cntc = (e_c - s_c) * CH;
        int j = 0;
        for (int i = tid; i < cntc; i += 256, ++j) {
            int k = s_c + i / CH, c = i % CH;
            float cv, mv; int av;
            if (j < 4) { cv = cc[j]; mv = cm[j]; av = ca[j]; }
            else {
                cv = cin[(size_t)k * ROW + coloff + c];
                mv = mm[(size_t)k * 4 + g];
                av = aa[k];
            }
            sout[k * CH + c] = (t == 0) ? cv : fmaf(mv, sout[av * CH + c], cv);
        }
        __syncthreads();
        s = s_n; e = e_n;
    }
}

__global__ __launch_bounds__(256, 1) void k_down() {
    extern __shared__ float sout[];
    __shared__ int sls16[404];
    __shared__ int s_nlvl;
    int ci = blockIdx.x, g = blockIdx.y, b = blockIdx.z;
    int c0 = ci * 8;
    int coloff = g * 65 + c0;
    int tid = threadIdx.x;
    if (tid == 0) s_nlvl = g_nlvl[b];
    __syncthreads();
    int nlvl = s_nlvl;
    int nph = (nlvl + 15) / 16;
    const int* gls = g_ls + b * (Nn + 2);
    for (int i = tid; i <= nph; i += 256) {
        int lev = 16 * i;
        sls16[i] = (lev == 0) ? 0 : ((lev >= nlvl) ? Nn : gls[lev]);
    }
    __syncthreads();
    const float* cin = g_cA + (size_t)b * Nn * ROW;
    const float* mm  = g_m1 + (size_t)b * Nn * 4;
    const int*   aa  = g_anc1 + (size_t)b * Nn;

    if (ci < 8) {
        down_core<8>(sout, cin, mm, aa, sls16, nph, coloff, g, tid);
        for (int k = tid; k < Nn; k += 256) {
            float* dst = g_cB + ((size_t)b * Nn + k) * ROW + coloff;
#pragma unroll
            for (int c = 0; c < 8; ++c) dst[c] = sout[k * 8 + c];
        }
    } else {
        down_core<1>(sout, cin, mm, aa, sls16, nph, coloff, g, tid);
        for (int k = tid; k < Nn; k += 256)
            g_cB[((size_t)b * Nn + k) * ROW + coloff] = sout[k];
    }
}

// ---------------- K5: normalize + un-permute + residual ----------------
__global__ __launch_bounds__(256) void k_final(const float* __restrict__ feat,
                                               const float* __restrict__ gammap,
                                               float* __restrict__ out) {
    __shared__ float tile[32 * 261];
    __shared__ int kq[32];
    int b = blockIdx.y, n0 = blockIdx.x * 32;
    int tid = threadIdx.x;
    if (tid < 32) kq[tid] = g_inv[b * Nn + n0 + tid];
    __syncthreads();
    for (int i = tid; i < 32 * 260; i += 256) {
        int r = i / 260, cc = i - r * 260;
        tile[r * 261 + cc] = g_cB[((size_t)b * Nn + kq[r]) * ROW + cc];
    }
    __syncthreads();
    float gamma = gammap[0];
    int nl = tid & 31;
    int cg = tid >> 5;
    for (int c = cg; c < 256; c += 8) {
        int gr = c >> 6, j = c & 63;
        float filt = tile[nl * 261 + gr * 65 + j];
        float norm = tile[nl * 261 + gr * 65 + 64];
        float res = filt / (EPSV + norm);
        size_t idx = ((size_t)b * CIN + c) * Nn + n0 + nl;
        out[idx] = fmaf(gamma, res, feat[idx]);
    }
}

// ---------------- launcher ----------------
extern "C" void kernel_launch(void* const* d_in, const int* in_sizes, int n_in,
                              void* d_out, int out_size) {
    const float* feature = (const float*)d_in[0];
    const float* guide   = (const float*)d_in[1];
    const float* We      = (const float*)d_in[2];
    const float* Wc      = (const float*)d_in[3];
    const float* Wg      = (const float*)d_in[4];
    const float* beta    = (const float*)d_in[5];
    const float* gamma   = (const float*)d_in[6];
    const int*   order   = (const int*)d_in[7];
    const int*   parent  = (const int*)d_in[8];
    float* out = (float*)d_out;

    cudaFuncSetAttribute(k_levels, cudaFuncAttributeMaxDynamicSharedMemorySize, 4 * Nn * 4);
    cudaFuncSetAttribute(k_up,     cudaFuncAttributeMaxDynamicSharedMemorySize, Nn * 8 * 4);
    cudaFuncSetAttribute(k_down,   cudaFuncAttributeMaxDynamicSharedMemorySize, Nn * 8 * 4);

    float* cA = nullptr; float* cB = nullptr;
    float* m0 = nullptr; float* m1 = nullptr;
    int* a0 = nullptr; int* a1 = nullptr;
    cudaGetSymbolAddress((void**)&cA, g_cA);
    cudaGetSymbolAddress((void**)&cB, g_cB);
    cudaGetSymbolAddress((void**)&m0, g_m0);
    cudaGetSymbolAddress((void**)&m1, g_m1);
    cudaGetSymbolAddress((void**)&a0, g_anc0);
    cudaGetSymbolAddress((void**)&a1, g_anc1);

    k_transpose<<<dim3(Nn / 32, CIN / 32, Bn), dim3(32, 8)>>>(feature);
    k_levels<<<Bn, 256, 4 * Nn * 4>>>(order, parent);
    k_gemm<<<dim3(Nn / 128, Bn, 2), 256>>>(feature, guide, We, Wc, Wg);
    k_w<<<dim3(Nn * 2 / 256, Bn), 256>>>(order, parent, beta);
    k_jump<<<Bn, 1024>>>(parent);
    k_up<<<dim3(9, Gn, Bn), 256, Nn * 8 * 4>>>(order, parent);
    k_double<1><<<dim3(Nn / 2, Bn), 256>>>(cA, cB, nullptr, m0, nullptr, a0, parent);
    k_double<0><<<dim3(Nn / 2, Bn), 256>>>(cB, cA, m0, m1, a0, a1, parent);
    k_double<0><<<dim3(Nn / 2, Bn), 256>>>(cA, cB, m1, m0, a1, a0, parent);
    k_double<0><<<dim3(Nn / 2, Bn), 256>>>(cB, cA, m0, m1, a0, a1, parent);
    k_down<<<dim3(9, Gn, Bn), 256, Nn * 8 * 4>>>();
    k_final<<<dim3(Nn / 32, Bn), 256>>>(feature, gamma, out);
}

// round 6
// speedup vs baseline: 1.6953x; 1.6953x over previous
#include <cuda_runtime.h>
#include <math.h>

#define Bn   4
#define CIN  256
#define CE   64
#define Gn   4
#define Hn   80
#define Wn   80
#define Nn   (Hn*Wn)        // 6400
#define ROW  260            // G * 65
#define EPSV 1e-8f

// ---------------- static device scratch ----------------
__device__ float g_ft   [Bn*Nn*CIN];
__device__ float g_embt [Bn*Nn*CE];
__device__ float g_gembt[Bn*Nn*CE];
__device__ float g_conf [Bn*Nn*Gn];
__device__ float g_w    [Bn*Gn*Nn];
__device__ float g_cA   [Bn*Nn*ROW];      // ping
__device__ float g_cB   [Bn*Nn*ROW];      // pong
__device__ float g_jm   [Bn*4*Gn*Nn];     // archived multipliers [b][slot][g][k]; slot s = stride 2^(s+1)
__device__ int   g_janc [Bn*4*Nn];        // archived ancestors   [b][slot][k]
__device__ int   g_inv  [Bn*Nn];
__device__ int   g_ls   [Bn*(Nn+2)];
__device__ int   g_nlvl [Bn];

// ---------------- packed f32x2 FMA ----------------
__device__ __forceinline__ void ffma2(unsigned long long &d,
                                      unsigned long long a,
                                      unsigned long long b) {
    asm("fma.rn.f32x2 %0, %1, %2, %0;" : "+l"(d) : "l"(a), "l"(b));
}

// ---------------- K0: transpose feature (b,c,n) -> (b,n,c) ----------------
__global__ void k_transpose(const float* __restrict__ f) {
    __shared__ float t[32][33];
    int b = blockIdx.z, c0 = blockIdx.y * 32, n0 = blockIdx.x * 32;
    int tx = threadIdx.x, ty = threadIdx.y;
    const float* src = f + ((size_t)b * CIN + c0) * Nn + n0;
#pragma unroll
    for (int r = 0; r < 32; r += 8)
        t[ty + r][tx] = src[(size_t)(ty + r) * Nn + tx];
    __syncthreads();
    float* dst = g_ft + ((size_t)b * Nn + n0) * CIN + c0;
#pragma unroll
    for (int r = 0; r < 32; r += 8)
        dst[(size_t)(ty + r) * CIN + tx] = t[tx][ty + r];
}

// ---------------- K1: levels (pointer doubling, early exit) + inverse perm ----------------
__global__ __launch_bounds__(256) void k_levels(const int* __restrict__ order,
                                                const int* __restrict__ parent) {
    extern __shared__ int sh[];
    int* a0 = sh;
    int* a1 = sh + Nn;
    int* l0 = sh + 2 * Nn;
    int* l1 = sh + 3 * Nn;
    __shared__ int s_more;
    int b = blockIdx.x, tid = threadIdx.x;
    const int* pp = parent + b * Nn;
    const int* od = order + b * Nn;
    for (int k = tid; k < Nn; k += blockDim.x) {
        a0[k] = pp[k];
        l0[k] = (k == 0) ? 0 : 1;
        g_inv[b * Nn + od[k]] = k;
    }
    __syncthreads();
    int* aa = a0; int* ab = a1; int* la = l0; int* lb = l1;
    for (int it = 0; it < 13; ++it) {
        if (tid == 0) s_more = 0;
        __syncthreads();
        int any = 0;
        for (int k = tid; k < Nn; k += blockDim.x) {
            int a = aa[k];
            lb[k] = la[k] + la[a];
            int na = aa[a];
            ab[k] = na;
            any |= na;
        }
        if (any) s_more = 1;
        __syncthreads();
        int* tmp = aa; aa = ab; ab = tmp;
        tmp = la; la = lb; lb = tmp;
        if (!s_more) break;
    }
    int* ls = g_ls + b * (Nn + 2);
    for (int k = tid; k < Nn; k += blockDim.x) {
        if (k == 0) ls[0] = 0;
        else if (la[k] != la[k - 1]) ls[la[k]] = k;
        if (k == Nn - 1) { g_nlvl[b] = la[k] + 1; ls[la[k] + 1] = Nn; }
    }
}

// ---------------- K2: skinny GEMMs via packed f32x2 FMA ----------------
__global__ __launch_bounds__(256) void k_gemm(const float* __restrict__ feat,
                                              const float* __restrict__ guide,
                                              const float* __restrict__ We,
                                              const float* __restrict__ Wc,
                                              const float* __restrict__ Wg) {
    __shared__ char smraw[34816];
    float*  xs = reinterpret_cast<float*>(smraw);
    float2* ws = reinterpret_cast<float2*>(smraw + 16384);
    float*  stage = reinterpret_cast<float*>(smraw);

    int tid = threadIdx.x;
    int os = tid >> 5;
    int nq = tid & 31;
    int n0 = blockIdx.x * 128;
    int b  = blockIdx.y;
    int path = blockIdx.z;

    const float* X = (path == 0 ? feat : guide) + (size_t)b * CIN * Nn;

    unsigned long long acc[9][2];
#pragma unroll
    for (int j = 0; j < 9; ++j) { acc[j][0] = 0ull; acc[j][1] = 0ull; }

    for (int kc = 0; kc < 256; kc += 32) {
        const float* Xb = X + (size_t)kc * Nn + n0;
#pragma unroll
        for (int i = tid; i < 1024; i += 256) {
            int kk = i >> 5, c4 = i & 31;
            *reinterpret_cast<float4*>(&xs[kk * 128 + c4 * 4]) =
                *reinterpret_cast<const float4*>(&Xb[(size_t)kk * Nn + c4 * 4]);
        }
#pragma unroll
        for (int i = tid; i < 2304; i += 256) {
            int o = i >> 5, kk = i & 31;
            float v = 0.f;
            if (path == 0) {
                if (o < 64)       v = We[o * 256 + kc + kk];
                else if (o < 68)  v = Wc[(o - 64) * 256 + kc + kk];
            } else {
                if (o < 64)       v = Wg[o * 256 + kc + kk];
            }
            ws[i] = make_float2(v, v);
        }
        __syncthreads();
#pragma unroll 2
        for (int kk = 0; kk < 32; ++kk) {
            float4 x4 = *reinterpret_cast<const float4*>(&xs[kk * 128 + nq * 4]);
            unsigned long long xlo = *reinterpret_cast<unsigned long long*>(&x4.x);
            unsigned long long xhi = *reinterpret_cast<unsigned long long*>(&x4.z);
#pragma unroll
            for (int j = 0; j < 9; ++j) {
                float2 wv = ws[(os * 9 + j) * 32 + kk];
                unsigned long long wp = *reinterpret_cast<unsigned long long*>(&wv);
                ffma2(acc[j][0], xlo, wp);
                ffma2(acc[j][1], xhi, wp);
            }
        }
        __syncthreads();
    }
#pragma unroll
    for (int j = 0; j < 9; ++j) {
        int o = os * 9 + j;
        if (o < 68) {
            float2 lo = *reinterpret_cast<float2*>(&acc[j][0]);
            float2 hi = *reinterpret_cast<float2*>(&acc[j][1]);
            stage[(nq * 4 + 0) * 68 + o] = lo.x;
            stage[(nq * 4 + 1) * 68 + o] = lo.y;
            stage[(nq * 4 + 2) * 68 + o] = hi.x;
            stage[(nq * 4 + 3) * 68 + o] = hi.y;
        }
    }
    __syncthreads();
    float* outt = (path == 0) ? g_embt : g_gembt;
#pragma unroll
    for (int i = tid; i < 2048; i += 256) {
        int n = i >> 4, c4 = i & 15;
        float4 v = *reinterpret_cast<float4*>(&stage[n * 68 + c4 * 4]);
        *reinterpret_cast<float4*>(&outt[((size_t)b * Nn + n0 + n) * 64 + c4 * 4]) = v;
    }
    if (path == 0) {
#pragma unroll
        for (int i = tid; i < 512; i += 256) {
            int n = i >> 2, gg = i & 3;
            float x = stage[n * 68 + 64 + gg];
            g_conf[((size_t)b * Nn + n0 + n) * 4 + gg] = 1.f / (1.f + expf(-x));
        }
    }
}

// ---------------- K3: edge weights, 2 threads per node ----------------
__global__ __launch_bounds__(256) void k_w(const int* __restrict__ order,
                                           const int* __restrict__ parent,
                                           const float* __restrict__ beta) {
    int b = blockIdx.y;
    int idx = blockIdx.x * 256 + threadIdx.x;
    int k = idx >> 1, half = idx & 1;
    if (k >= Nn) return;
    int n1 = order[b * Nn + k];
    int p  = parent[b * Nn + k];
    int n0 = order[b * Nn + p];
    int coff = half * 32;
    const float4* e1 = reinterpret_cast<const float4*>(g_embt  + ((size_t)b * Nn + n1) * 64 + coff);
    const float4* e0 = reinterpret_cast<const float4*>(g_embt  + ((size_t)b * Nn + n0) * 64 + coff);
    const float4* q1 = reinterpret_cast<const float4*>(g_gembt + ((size_t)b * Nn + n1) * 64 + coff);
    const float4* q0 = reinterpret_cast<const float4*>(g_gembt + ((size_t)b * Nn + n0) * 64 + coff);
    float d[2] = {0.f, 0.f};
#pragma unroll
    for (int i = 0; i < 8; ++i) {
        float4 a = e1[i], c = e0[i];
        float dx = a.x - c.x, dy = a.y - c.y, dz = a.z - c.z, dw = a.w - c.w;
        d[i >> 2] += dx * dx + dy * dy + dz * dz + dw * dw;
    }
#pragma unroll
    for (int i = 0; i < 8; ++i) {
        float4 a = q1[i], c = q0[i];
        float dx = a.x - c.x, dy = a.y - c.y, dz = a.z - c.z, dw = a.w - c.w;
        d[i >> 2] += dx * dx + dy * dy + dz * dz + dw * dw;
    }
#pragma unroll
    for (int j = 0; j < 2; ++j) {
        int g = half * 2 + j;
        float bb = beta[g];
        g_w[((size_t)b * 4 + g) * Nn + k] = expf(-(d[j] + bb * bb));
    }
}

// ---------------- K4a: init y = gathered x (in BFS order) in g_cA; zero g_cB ----------------
__global__ __launch_bounds__(256) void k_init(const int* __restrict__ order) {
    int b = blockIdx.y;
    int k = blockIdx.x * 2 + (threadIdx.x >> 7);
    int t = threadIdx.x & 127;
    int n = order[b * Nn + k];
    const float* cf4 = g_conf + ((size_t)b * Nn + n) * 4;
    const float* fr  = g_ft + ((size_t)b * Nn + n) * CIN;
    float* ya = g_cA + ((size_t)b * Nn + k) * ROW;
    float* yb = g_cB + ((size_t)b * Nn + k) * ROW;
#pragma unroll
    for (int s = 0; s < 3; ++s) {
        int ch = t + 128 * s;
        if (ch < ROW) {
            int g = ch / 65, j = ch - g * 65;
            float cf = cf4[g];
            float v = (j == 64) ? cf : fr[g * 64 + j] * cf;
            ya[ch] = v;
            yb[ch] = 0.f;
        }
    }
}

// ---------------- K4b: up scatter pass P (stride 2^P), fused table doubling -> slot P ----------------
// y_out[anc] += m*y_in[k]; y_out[k] += y_in[k]; y_in zeroed after read.
template<int P>
__global__ __launch_bounds__(256) void k_scat(const int* __restrict__ parent,
                                              const float* __restrict__ yin_,
                                              float* __restrict__ yout_) {
    int b = blockIdx.y;
    int k = blockIdx.x * 2 + (threadIdx.x >> 7);
    int t = threadIdx.x & 127;
    int anc;
    float m[4];
    if (P == 0) {
        anc = parent[b * Nn + k];
#pragma unroll
        for (int g = 0; g < 4; ++g)
            m[g] = (k == 0) ? 0.f : g_w[((size_t)b * 4 + g) * Nn + k];
    } else {
        anc = g_janc[(b * 4 + (P - 1)) * Nn + k];
#pragma unroll
        for (int g = 0; g < 4; ++g)
            m[g] = g_jm[(((size_t)(b * 4) + (P - 1)) * 4 + g) * Nn + k];
    }
    const float* yi = yin_ + ((size_t)b * Nn + k) * ROW;
    float* yo_k = yout_ + ((size_t)b * Nn + k) * ROW;
    float* yo_a = yout_ + ((size_t)b * Nn + anc) * ROW;
    float* yi_w = const_cast<float*>(yi);
#pragma unroll
    for (int s = 0; s < 3; ++s) {
        int ch = t + 128 * s;
        if (ch < ROW) {
            int g = ch / 65;
            float v = yi[ch];
            yi_w[ch] = 0.f;
            atomicAdd(&yo_k[ch], v);
            float mg = m[g];
            if (mg != 0.f) atomicAdd(&yo_a[ch], mg * v);
        }
    }
    // table doubling: stride 2^(P+1) -> slot P
    if (t < 4) {
        float ma;
        if (P == 0) ma = (anc == 0) ? 0.f : g_w[((size_t)b * 4 + t) * Nn + anc];
        else        ma = g_jm[(((size_t)(b * 4) + (P - 1)) * 4 + t) * Nn + anc];
        g_jm[(((size_t)(b * 4) + P) * 4 + t) * Nn + k] = m[t] * ma;
    }
    if (t == 4) {
        int a2 = (P == 0) ? parent[b * Nn + anc] : g_janc[(b * 4 + (P - 1)) * Nn + anc];
        g_janc[(b * 4 + P) * Nn + k] = a2;
    }
}

// ---------------- K4c: up-tail (stride-16 condensed up-sweep in smem) + c2 epilogue ----------------
template<int CH>
__device__ __forceinline__ void uptail_core(float* sagg, const float* __restrict__ m16,
                                            const int* __restrict__ a16,
                                            const int* sls16, int nph, int tid) {
    if (nph <= 1) return;
    float rw[4]; int rp[4];
    int j = nph - 1;
    int s = sls16[j], e = sls16[j + 1];
    int cnt = (e - s) * CH;
#pragma unroll
    for (int q = 0; q < 4; ++q) {
        int i = tid + 256 * q;
        if (i < cnt) { int k = s + i / CH; rp[q] = a16[k]; rw[q] = m16[k]; }
    }
    while (j >= 1) {
        int s_c = s, e_c = e;
        float wc[4]; int pc[4];
#pragma unroll
        for (int q = 0; q < 4; ++q) { wc[q] = rw[q]; pc[q] = rp[q]; }
        int j_n = j - 1;
        int s_n = 0;
        if (j_n >= 1) {
            s_n = sls16[j_n];
            int cntn = (s_c - s_n) * CH;
#pragma unroll
            for (int q = 0; q < 4; ++q) {
                int i = tid + 256 * q;
                if (i < cntn) { int k = s_n + i / CH; rp[q] = a16[k]; rw[q] = m16[k]; }
            }
        }
        int cntc = (e_c - s_c) * CH;
        int q = 0;
        for (int i = tid; i < cntc; i += 256, ++q) {
            int k = s_c + i / CH, c = i % CH;
            float wv; int p;
            if (q < 4) { wv = wc[q]; p = pc[q]; }
            else       { p = a16[k]; wv = m16[k]; }
            atomicAdd(&sagg[p * CH + c], wv * sagg[k * CH + c]);
        }
        __syncthreads();
        e = s_c; s = s_n; j = j_n;
    }
}

__global__ __launch_bounds__(256, 1) void k_uptail(const int* __restrict__ parent) {
    extern __shared__ float sagg[];
    __shared__ int sls16[404];
    __shared__ int s_nlvl;
    int ci = blockIdx.x, g = blockIdx.y, b = blockIdx.z;
    int c0 = ci * 8;
    int coloff = (ci < 8) ? (g * 65 + c0) : (g * 65 + 64);
    int tid = threadIdx.x;
    if (tid == 0) s_nlvl = g_nlvl[b];
    __syncthreads();
    int nlvl = s_nlvl;
    int nph = (nlvl + 15) / 16;
    const int* gls = g_ls + b * (Nn + 2);
    for (int i = tid; i <= nph; i += 256) {
        int lev = 16 * i;
        sls16[i] = (lev == 0) ? 0 : ((lev >= nlvl) ? Nn : gls[lev]);
    }
    const float* m16 = g_jm + (((size_t)(b * 4) + 3) * 4 + g) * Nn;
    const int*   a16 = g_janc + (b * 4 + 3) * Nn;
    const int*   pp  = parent + b * Nn;
    const float* gw  = g_w + ((size_t)b * 4 + g) * Nn;
    const float* yin = g_cA + (size_t)b * Nn * ROW;
    float* yout = g_cB + (size_t)b * Nn * ROW;

    if (ci < 8) {
        for (int k = tid; k < Nn; k += 256) {
            const float* src = yin + (size_t)k * ROW + coloff;
#pragma unroll
            for (int c = 0; c < 8; ++c) sagg[k * 8 + c] = src[c];
        }
        __syncthreads();
        uptail_core<8>(sagg, m16, a16, sls16, nph, tid);
        // epilogue: c2 = f_k*agg_k + w_k*f_p*agg_p  (composed stride-1 and stride... -> stride 2 base)
        for (int k = tid; k < Nn; k += 256) {
            float wk = (k == 0) ? 0.f : gw[k];
            int p = pp[k];
            float wp = (p == 0) ? 0.f : gw[p];
            float fk = 1.f - wk * wk;
            float fp = 1.f - wp * wp;
            float* dst = yout + (size_t)k * ROW + coloff;
#pragma unroll
            for (int c = 0; c < 8; ++c)
                dst[c] = fmaf(wk * fp, sagg[p * 8 + c], fk * sagg[k * 8 + c]);
        }
    } else {
        for (int k = tid; k < Nn; k += 256)
            sagg[k] = yin[(size_t)k * ROW + coloff];
        __syncthreads();
        uptail_core<1>(sagg, m16, a16, sls16, nph, tid);
        for (int k = tid; k < Nn; k += 256) {
            float wk = (k == 0) ? 0.f : gw[k];
            int p = pp[k];
            float wp = (p == 0) ? 0.f : gw[p];
            float fk = 1.f - wk * wk;
            float fp = 1.f - wp * wp;
            yout[(size_t)k * ROW + coloff] = fmaf(wk * fp, sagg[p], fk * sagg[k]);
        }
    }
}

// ---------------- K4d: c-composition gather pass using archived table slot ----------------
// c_out[k] = c_in[k] + m_slot[k] * c_in[anc_slot[k]]
__global__ __launch_bounds__(256) void k_cdouble(int slot,
                                                 const float* __restrict__ cin,
                                                 float* __restrict__ cout) {
    int b = blockIdx.y;
    int k = blockIdx.x * 2 + (threadIdx.x >> 7);
    int t = threadIdx.x & 127;
    int anc = g_janc[(b * 4 + slot) * Nn + k];
    const float* ck = cin + ((size_t)b * Nn + k) * ROW;
    const float* ca = cin + ((size_t)b * Nn + anc) * ROW;
    float* co = cout + ((size_t)b * Nn + k) * ROW;
    const float* mbase = g_jm + ((size_t)(b * 4) + slot) * 4 * Nn;
#pragma unroll
    for (int s = 0; s < 3; ++s) {
        int ch = t + 128 * s;
        if (ch < ROW) {
            int g = ch / 65;
            float m = mbase[(size_t)g * Nn + k];
            co[ch] = fmaf(m, ca[ch], ck[ch]);
        }
    }
}

// ---------------- K4e: strided down-sweep (16 levels per phase) ----------------
template<int CH>
__device__ __forceinline__ void down_core(float* sout, const float* __restrict__ cin,
                                          const float* __restrict__ mm,
                                          const int* __restrict__ aa,
                                          const int* sls16, int nph,
                                          int coloff, int tid) {
    float rc[4], rm[4]; int ra[4];
    int s = sls16[0], e = sls16[1];
    {
        int cnt = (e - s) * CH;
#pragma unroll
        for (int j = 0; j < 4; ++j) {
            int i = tid + 256 * j;
            if (i < cnt) {
                int k = s + i / CH, c = i % CH;
                rc[j] = cin[(size_t)k * ROW + coloff + c];
                rm[j] = mm[k];
                ra[j] = aa[k];
            }
        }
    }
    for (int t = 0; t < nph; ++t) {
        int s_c = s, e_c = e;
        float cc[4], cm[4]; int ca[4];
#pragma unroll
        for (int j = 0; j < 4; ++j) { cc[j] = rc[j]; cm[j] = rm[j]; ca[j] = ra[j]; }
        int s_n = 0, e_n = 0;
        if (t + 1 < nph) {
            s_n = sls16[t + 1]; e_n = sls16[t + 2];
            int cntn = (e_n - s_n) * CH;
#pragma unroll
            for (int j = 0; j < 4; ++j) {
                int i = tid + 256 * j;
                if (i < cntn) {
                    int k = s_n + i / CH, c = i % CH;
                    rc[j] = cin[(size_t)k * ROW + coloff + c];
                    rm[j] = mm[k];
                    ra[j] = aa[k];
                }
            }
        }
        int cntc = (e_c - s_c) * CH;
        int j = 0;
        for (int i = tid; i < cntc; i += 256, ++j) {
            int k = s_c + i / CH, c = i % CH;
            float cv, mv; int av;
            if (j < 4) { cv = cc[j]; mv = cm[j]; av = ca[j]; }
            else {
                cv = cin[(size_t)k * ROW + coloff + c];
                mv = mm[k];
                av = aa[k];
            }
            sout[k * CH + c] = (t == 0) ? cv : fmaf(mv, sout[av * CH + c], cv);
        }
        __syncthreads();
        s = s_n; e = e_n;
    }
}

__global__ __launch_bounds__(256, 1) void k_down() {
    extern __shared__ float sout[];
    __shared__ int sls16[404];
    __shared__ int s_nlvl;
    int ci = blockIdx.x, g = blockIdx.y, b = blockIdx.z;
    int c0 = ci * 8;
    int coloff = (ci < 8) ? (g * 65 + c0) : (g * 65 + 64);
    int tid = threadIdx.x;
    if (tid == 0) s_nlvl = g_nlvl[b];
    __syncthreads();
    int nlvl = s_nlvl;
    int nph = (nlvl + 15) / 16;
    const int* gls = g_ls + b * (Nn + 2);
    for (int i = tid; i <= nph; i += 256) {
        int lev = 16 * i;
        sls16[i] = (lev == 0) ? 0 : ((lev >= nlvl) ? Nn : gls[lev]);
    }
    __syncthreads();
    const float* cin = g_cA + (size_t)b * Nn * ROW;
    const float* mm  = g_jm + (((size_t)(b * 4) + 3) * 4 + g) * Nn;
    const int*   aa  = g_janc + (b * 4 + 3) * Nn;

    if (ci < 8) {
        down_core<8>(sout, cin, mm, aa, sls16, nph, coloff, tid);
        for (int k = tid; k < Nn; k += 256) {
            float* dst = g_cB + ((size_t)b * Nn + k) * ROW + coloff;
#pragma unroll
            for (int c = 0; c < 8; ++c) dst[c] = sout[k * 8 + c];
        }
    } else {
        down_core<1>(sout, cin, mm, aa, sls16, nph, coloff, tid);
        for (int k = tid; k < Nn; k += 256)
            g_cB[((size_t)b * Nn + k) * ROW + coloff] = sout[k];
    }
}

// ---------------- K5: normalize + un-permute + residual ----------------
__global__ __launch_bounds__(256) void k_final(const float* __restrict__ feat,
                                               const float* __restrict__ gammap,
                                               float* __restrict__ out) {
    __shared__ float tile[32 * 261];
    __shared__ int kq[32];
    int b = blockIdx.y, n0 = blockIdx.x * 32;
    int tid = threadIdx.x;
    if (tid < 32) kq[tid] = g_inv[b * Nn + n0 + tid];
    __syncthreads();
    for (int i = tid; i < 32 * 260; i += 256) {
        int r = i / 260, cc = i - r * 260;
        tile[r * 261 + cc] = g_cB[((size_t)b * Nn + kq[r]) * ROW + cc];
    }
    __syncthreads();
    float gamma = gammap[0];
    int nl = tid & 31;
    int cg = tid >> 5;
    for (int c = cg; c < 256; c += 8) {
        int gr = c >> 6, j = c & 63;
        float filt = tile[nl * 261 + gr * 65 + j];
        float norm = tile[nl * 261 + gr * 65 + 64];
        float res = filt / (EPSV + norm);
        size_t idx = ((size_t)b * CIN + c) * Nn + n0 + nl;
        out[idx] = fmaf(gamma, res, feat[idx]);
    }
}

// ---------------- launcher ----------------
extern "C" void kernel_launch(void* const* d_in, const int* in_sizes, int n_in,
                              void* d_out, int out_size) {
    const float* feature = (const float*)d_in[0];
    const float* guide   = (const float*)d_in[1];
    const float* We      = (const float*)d_in[2];
    const float* Wc      = (const float*)d_in[3];
    const float* Wg      = (const float*)d_in[4];
    const float* beta    = (const float*)d_in[5];
    const float* gamma   = (const float*)d_in[6];
    const int*   order   = (const int*)d_in[7];
    const int*   parent  = (const int*)d_in[8];
    float* out = (float*)d_out;

    cudaFuncSetAttribute(k_levels, cudaFuncAttributeMaxDynamicSharedMemorySize, 4 * Nn * 4);
    cudaFuncSetAttribute(k_uptail, cudaFuncAttributeMaxDynamicSharedMemorySize, Nn * 8 * 4);
    cudaFuncSetAttribute(k_down,   cudaFuncAttributeMaxDynamicSharedMemorySize, Nn * 8 * 4);

    float* cA = nullptr; float* cB = nullptr;
    cudaGetSymbolAddress((void**)&cA, g_cA);
    cudaGetSymbolAddress((void**)&cB, g_cB);

    dim3 rows2(Nn / 2, Bn);

    k_transpose<<<dim3(Nn / 32, CIN / 32, Bn), dim3(32, 8)>>>(feature);
    k_levels<<<Bn, 256, 4 * Nn * 4>>>(order, parent);
    k_gemm<<<dim3(Nn / 128, Bn, 2), 256>>>(feature, guide, We, Wc, Wg);
    k_w<<<dim3(Nn * 2 / 256, Bn), 256>>>(order, parent, beta);
    k_init<<<rows2, 256>>>(order);
    // up-sweep: 4 global scatter passes, strides 1,2,4,8 (tables -> slots 0..3 = strides 2,4,8,16)
    k_scat<0><<<rows2, 256>>>(parent, cA, cB);   // A -> B  (A zeroed)
    k_scat<1><<<rows2, 256>>>(parent, cB, cA);   // B -> A  (B zeroed)
    k_scat<2><<<rows2, 256>>>(parent, cA, cB);   // A -> B
    k_scat<3><<<rows2, 256>>>(parent, cB, cA);   // B -> A : y (depth<16 sums) in A
    // stride-16 condensed up-sweep in smem; epilogue writes c2 (stride-2 composed c) into B
    k_uptail<<<dim3(9, Gn, Bn), 256, Nn * 8 * 4>>>(parent);
    // compose c: stride 2 -> 4 -> 8 -> 16 using archived tables (slots 0,1,2)
    k_cdouble<<<rows2, 256>>>(0, cB, cA);        // c2 (+ stride2 jump) -> c4 in A
    k_cdouble<<<rows2, 256>>>(1, cA, cB);        // -> c8 in B
    k_cdouble<<<rows2, 256>>>(2, cB, cA);        // -> c16 in A
    k_down<<<dim3(9, Gn, Bn), 256, Nn * 8 * 4>>>();
    k_final<<<dim3(Nn / 32, Bn), 256>>>(feature, gamma, out);
}

// round 7
// speedup vs baseline: 2.2955x; 1.3541x over previous
#include <cuda_runtime.h>
#include <math.h>

#define Bn   4
#define CIN  256
#define CE   64
#define Gn   4
#define Hn   80
#define Wn   80
#define Nn   (Hn*Wn)        // 6400
#define NCH  65             // channel chunks of 4 (16 per group + 1 norm chunk)
#define EPSV 1e-8f

// ---------------- static device scratch ----------------
__device__ float  g_ft   [Bn*Nn*CIN];     // feature transposed (b, n, c)
__device__ float  g_embt [Bn*Nn*CE];
__device__ float  g_gembt[Bn*Nn*CE];
__device__ float  g_conf [Bn*Nn*Gn];      // (b, n, g) float4-readable
__device__ float  g_w    [Bn*Gn*Nn];      // (b, g, k) BFS order
__device__ float4 g_cC   [Bn*NCH*Nn];     // chunked scan data [b][chunk][k] (4 ch)
__device__ float4 g_jm   [Bn*5*Nn];       // multipliers [b][slot][k].(g)  slot s: stride 2^s
__device__ int    g_janc [Bn*5*Nn];       // ancestors   [b][slot][k]
__device__ int    g_rs   [Bn*5*Nn];       // descendant-range start [b][slot][k]
__device__ int    g_re   [Bn*5*Nn];       // descendant-range end
__device__ int    g_inv  [Bn*Nn];
__device__ int    g_ls   [Bn*(Nn+2)];
__device__ int    g_nlvl [Bn];

// ---------------- packed f32x2 FMA ----------------
__device__ __forceinline__ void ffma2(unsigned long long &d,
                                      unsigned long long a,
                                      unsigned long long b) {
    asm("fma.rn.f32x2 %0, %1, %2, %0;" : "+l"(d) : "l"(a), "l"(b));
}

// ---------------- K1: skinny GEMMs via packed f32x2 FMA ----------------
__global__ __launch_bounds__(256) void k_gemm(const float* __restrict__ feat,
                                              const float* __restrict__ guide,
                                              const float* __restrict__ We,
                                              const float* __restrict__ Wc,
                                              const float* __restrict__ Wg) {
    __shared__ char smraw[34816];
    float*  xs = reinterpret_cast<float*>(smraw);
    float2* ws = reinterpret_cast<float2*>(smraw + 16384);
    float*  stage = reinterpret_cast<float*>(smraw);

    int tid = threadIdx.x;
    int os = tid >> 5;
    int nq = tid & 31;
    int n0 = blockIdx.x * 128;
    int b  = blockIdx.y;
    int path = blockIdx.z;

    const float* X = (path == 0 ? feat : guide) + (size_t)b * CIN * Nn;

    unsigned long long acc[9][2];
#pragma unroll
    for (int j = 0; j < 9; ++j) { acc[j][0] = 0ull; acc[j][1] = 0ull; }

    for (int kc = 0; kc < 256; kc += 32) {
        const float* Xb = X + (size_t)kc * Nn + n0;
#pragma unroll
        for (int i = tid; i < 1024; i += 256) {
            int kk = i >> 5, c4 = i & 31;
            *reinterpret_cast<float4*>(&xs[kk * 128 + c4 * 4]) =
                *reinterpret_cast<const float4*>(&Xb[(size_t)kk * Nn + c4 * 4]);
        }
#pragma unroll
        for (int i = tid; i < 2304; i += 256) {
            int o = i >> 5, kk = i & 31;
            float v = 0.f;
            if (path == 0) {
                if (o < 64)       v = We[o * 256 + kc + kk];
                else if (o < 68)  v = Wc[(o - 64) * 256 + kc + kk];
            } else {
                if (o < 64)       v = Wg[o * 256 + kc + kk];
            }
            ws[i] = make_float2(v, v);
        }
        __syncthreads();
#pragma unroll 2
        for (int kk = 0; kk < 32; ++kk) {
            float4 x4 = *reinterpret_cast<const float4*>(&xs[kk * 128 + nq * 4]);
            unsigned long long xlo = *reinterpret_cast<unsigned long long*>(&x4.x);
            unsigned long long xhi = *reinterpret_cast<unsigned long long*>(&x4.z);
#pragma unroll
            for (int j = 0; j < 9; ++j) {
                float2 wv = ws[(os * 9 + j) * 32 + kk];
                unsigned long long wp = *reinterpret_cast<unsigned long long*>(&wv);
                ffma2(acc[j][0], xlo, wp);
                ffma2(acc[j][1], xhi, wp);
            }
        }
        __syncthreads();
    }
#pragma unroll
    for (int j = 0; j < 9; ++j) {
        int o = os * 9 + j;
        if (o < 68) {
            float2 lo = *reinterpret_cast<float2*>(&acc[j][0]);
            float2 hi = *reinterpret_cast<float2*>(&acc[j][1]);
            stage[(nq * 4 + 0) * 68 + o] = lo.x;
            stage[(nq * 4 + 1) * 68 + o] = lo.y;
            stage[(nq * 4 + 2) * 68 + o] = hi.x;
            stage[(nq * 4 + 3) * 68 + o] = hi.y;
        }
    }
    __syncthreads();
    float* outt = (path == 0) ? g_embt : g_gembt;
#pragma unroll
    for (int i = tid; i < 2048; i += 256) {
        int n = i >> 4, c4 = i & 15;
        float4 v = *reinterpret_cast<float4*>(&stage[n * 68 + c4 * 4]);
        *reinterpret_cast<float4*>(&outt[((size_t)b * Nn + n0 + n) * 64 + c4 * 4]) = v;
    }
    if (path == 0) {
#pragma unroll
        for (int i = tid; i < 512; i += 256) {
            int n = i >> 2, gg = i & 3;
            float x = stage[n * 68 + 64 + gg];
            g_conf[((size_t)b * Nn + n0 + n) * 4 + gg] = 1.f / (1.f + expf(-x));
        }
    }
}

// ---------------- K2: edge weights, 2 threads per node ----------------
__global__ __launch_bounds__(256) void k_w(const int* __restrict__ order,
                                           const int* __restrict__ parent,
                                           const float* __restrict__ beta) {
    int b = blockIdx.y;
    int idx = blockIdx.x * 256 + threadIdx.x;
    int k = idx >> 1, half = idx & 1;
    if (k >= Nn) return;
    int n1 = order[b * Nn + k];
    int p  = parent[b * Nn + k];
    int n0 = order[b * Nn + p];
    int coff = half * 32;
    const float4* e1 = reinterpret_cast<const float4*>(g_embt  + ((size_t)b * Nn + n1) * 64 + coff);
    const float4* e0 = reinterpret_cast<const float4*>(g_embt  + ((size_t)b * Nn + n0) * 64 + coff);
    const float4* q1 = reinterpret_cast<const float4*>(g_gembt + ((size_t)b * Nn + n1) * 64 + coff);
    const float4* q0 = reinterpret_cast<const float4*>(g_gembt + ((size_t)b * Nn + n0) * 64 + coff);
    float d[2] = {0.f, 0.f};
#pragma unroll
    for (int i = 0; i < 8; ++i) {
        float4 a = e1[i], c = e0[i];
        float dx = a.x - c.x, dy = a.y - c.y, dz = a.z - c.z, dw = a.w - c.w;
        d[i >> 2] += dx * dx + dy * dy + dz * dz + dw * dw;
    }
#pragma unroll
    for (int i = 0; i < 8; ++i) {
        float4 a = q1[i], c = q0[i];
        float dx = a.x - c.x, dy = a.y - c.y, dz = a.z - c.z, dw = a.w - c.w;
        d[i >> 2] += dx * dx + dy * dy + dz * dz + dw * dw;
    }
#pragma unroll
    for (int j = 0; j < 2; ++j) {
        int g = half * 2 + j;
        float bb = beta[g];
        g_w[((size_t)b * 4 + g) * Nn + k] = expf(-(d[j] + bb * bb));
    }
}

// ---------------- K3: fused transpose + levels + jump tables/ranges ----------------
// blocks [0, 6400): transpose; [6400, 6404): levels; [6404, 6408): tables
__global__ __launch_bounds__(256) void k_pretab(const float* __restrict__ feat,
                                                const int* __restrict__ order,
                                                const int* __restrict__ parent) {
    extern __shared__ int sh[];
    int bid = blockIdx.x;
    int tid = threadIdx.x;

    if (bid < 6400) {
        // -------- transpose role --------
        __shared__ float t[32][33];
        int b = bid / 1600;
        int r2 = bid - b * 1600;
        int c0 = (r2 / 200) * 32;
        int n0 = (r2 % 200) * 32;
        int tx = tid & 31, ty = tid >> 5;   // 32 x 8
        const float* src = feat + ((size_t)b * CIN + c0) * Nn + n0;
#pragma unroll
        for (int r = 0; r < 32; r += 8)
            t[ty + r][tx] = src[(size_t)(ty + r) * Nn + tx];
        __syncthreads();
        float* dst = g_ft + ((size_t)b * Nn + n0) * CIN + c0;
#pragma unroll
        for (int r = 0; r < 32; r += 8)
            dst[(size_t)(ty + r) * CIN + tx] = t[tx][ty + r];
        return;
    }

    if (bid < 6404) {
        // -------- levels role (pointer doubling in dynamic smem) --------
        int* a0 = sh;
        int* a1 = sh + Nn;
        int* l0 = sh + 2 * Nn;
        int* l1 = sh + 3 * Nn;
        __shared__ int s_more;
        int b = bid - 6400;
        const int* pp = parent + b * Nn;
        const int* od = order + b * Nn;
        for (int k = tid; k < Nn; k += 256) {
            a0[k] = pp[k];
            l0[k] = (k == 0) ? 0 : 1;
            g_inv[b * Nn + od[k]] = k;
        }
        __syncthreads();
        int* aa = a0; int* ab = a1; int* la = l0; int* lb = l1;
        for (int it = 0; it < 13; ++it) {
            if (tid == 0) s_more = 0;
            __syncthreads();
            int any = 0;
            for (int k = tid; k < Nn; k += 256) {
                int a = aa[k];
                lb[k] = la[k] + la[a];
                int na = aa[a];
                ab[k] = na;
                any |= na;
            }
            if (any) s_more = 1;
            __syncthreads();
            int* tmp = aa; aa = ab; ab = tmp;
            tmp = la; la = lb; lb = tmp;
            if (!s_more) break;
        }
        int* ls = g_ls + b * (Nn + 2);
        for (int k = tid; k < Nn; k += 256) {
            if (k == 0) ls[0] = 0;
            else if (la[k] != la[k - 1]) ls[la[k]] = k;
            if (k == Nn - 1) { g_nlvl[b] = la[k] + 1; ls[la[k] + 1] = Nn; }
        }
        return;
    }

    // -------- tables role: anc/m for strides 1,2,4,8,16 + descendant ranges --------
    {
        int b = bid - 6404;
        const int* pp = parent + b * Nn;
        int*    anc = g_janc + (size_t)b * 5 * Nn;
        float4* jm  = g_jm   + (size_t)b * 5 * Nn;
        // slot 0: stride 1
        for (int k = tid; k < Nn; k += 256) {
            anc[k] = pp[k];
            float4 mv;
            mv.x = (k == 0) ? 0.f : g_w[((size_t)b * 4 + 0) * Nn + k];
            mv.y = (k == 0) ? 0.f : g_w[((size_t)b * 4 + 1) * Nn + k];
            mv.z = (k == 0) ? 0.f : g_w[((size_t)b * 4 + 2) * Nn + k];
            mv.w = (k == 0) ? 0.f : g_w[((size_t)b * 4 + 3) * Nn + k];
            jm[k] = mv;
        }
        __syncthreads();
        // slots 1..4: doubling
        for (int s = 1; s < 5; ++s) {
            for (int k = tid; k < Nn; k += 256) {
                int a = anc[(s - 1) * Nn + k];
                anc[s * Nn + k] = anc[(s - 1) * Nn + a];
                float4 mk = jm[(s - 1) * Nn + k];
                float4 ma = jm[(s - 1) * Nn + a];
                float4 mo;
                mo.x = mk.x * ma.x; mo.y = mk.y * ma.y;
                mo.z = mk.z * ma.z; mo.w = mk.w * ma.w;
                jm[s * Nn + k] = mo;
            }
            __syncthreads();
        }
        // ranges
        int* rs = g_rs + (size_t)b * 5 * Nn;
        int* re = g_re + (size_t)b * 5 * Nn;
        for (int i = tid; i < 5 * Nn; i += 256) { rs[i] = 0; re[i] = 0; }
        __syncthreads();
        for (int s = 0; s < 5; ++s) {
            const int* as = anc + s * Nn;
            for (int j = tid; j < Nn; j += 256) {
                int a = as[j];
                int ap = (j > 0) ? as[j - 1] : -1;
                if (a != ap) {
                    rs[s * Nn + a] = j;
                    if (j > 0) re[s * Nn + ap] = j;
                }
                if (j == Nn - 1) re[s * Nn + a] = Nn;
            }
        }
    }
}

// ---------------- K4: up-sweep, all in smem, atomic-free gathers ----------------
// grid (65, Bn): chunk ci (<64: g=ci>>4, cols q*4 of group g; ==64: norm = conf per g)
template<bool NORM>
__device__ __forceinline__ void factor_pass(const float4* __restrict__ in,
                                            float4* __restrict__ out,
                                            const int* __restrict__ rs,
                                            const int* __restrict__ re,
                                            const float* __restrict__ jmS,
                                            const float4* __restrict__ jm4,
                                            int tid) {
    for (int k = tid; k < Nn; k += 256) {
        float4 acc = in[k];
        int lo = __ldg(&rs[k]), hi = __ldg(&re[k]);
        for (int j = lo; j < hi; ++j) {
            float4 x = in[j];
            if (NORM) {
                float4 m = __ldg(&jm4[j]);
                acc.x += m.x * x.x; acc.y += m.y * x.y;
                acc.z += m.z * x.z; acc.w += m.w * x.w;
            } else {
                float m = __ldg(&jmS[j * 4]);
                acc.x += m * x.x; acc.y += m * x.y;
                acc.z += m * x.z; acc.w += m * x.w;
            }
        }
        out[k] = acc;
    }
    __syncthreads();
}

template<bool NORM>
__device__ __forceinline__ void compose_pass(const float4* __restrict__ in,
                                             float4* __restrict__ out,
                                             const int* __restrict__ anc,
                                             const float* __restrict__ jmS,
                                             const float4* __restrict__ jm4,
                                             int tid) {
    for (int k = tid; k < Nn; k += 256) {
        int a = __ldg(&anc[k]);
        float4 ck = in[k];
        float4 ca = in[a];
        if (NORM) {
            float4 m = __ldg(&jm4[k]);
            ck.x += m.x * ca.x; ck.y += m.y * ca.y;
            ck.z += m.z * ca.z; ck.w += m.w * ca.w;
        } else {
            float m = __ldg(&jmS[k * 4]);
            ck.x += m * ca.x; ck.y += m * ca.y;
            ck.z += m * ca.z; ck.w += m * ca.w;
        }
        out[k] = ck;
    }
    __syncthreads();
}

__global__ __launch_bounds__(256, 1) void k_up(const int* __restrict__ order) {
    extern __shared__ float4 sm4[];
    float4* A = sm4;
    float4* Bf = sm4 + Nn;
    __shared__ int sls16[404];
    __shared__ int s_nlvl;
    int ci = blockIdx.x, b = blockIdx.y;
    int tid = threadIdx.x;
    bool norm = (ci == 64);
    int g = norm ? 0 : (ci >> 4);
    int q = ci & 15;

    if (tid == 0) s_nlvl = g_nlvl[b];
    __syncthreads();
    int nlvl = s_nlvl;
    int nb16 = (nlvl + 15) / 16;
    const int* gls = g_ls + b * (Nn + 2);
    for (int i = tid; i <= nb16; i += 256) {
        int lev = 16 * i;
        sls16[i] = (lev == 0) ? 0 : ((lev >= nlvl) ? Nn : gls[lev]);
    }

    // init: A[k] = gathered x
    const int* od = order + b * Nn;
    if (!norm) {
        int ftcol = g * 64 + q * 4;
        for (int k = tid; k < Nn; k += 256) {
            int n = od[k];
            float cf = g_conf[((size_t)b * Nn + n) * 4 + g];
            float4 v = *reinterpret_cast<const float4*>(g_ft + ((size_t)b * Nn + n) * CIN + ftcol);
            v.x *= cf; v.y *= cf; v.z *= cf; v.w *= cf;
            A[k] = v;
        }
    } else {
        for (int k = tid; k < Nn; k += 256) {
            int n = od[k];
            A[k] = *reinterpret_cast<const float4*>(g_conf + ((size_t)b * Nn + n) * 4);
        }
    }
    __syncthreads();

    const int*    rsb = g_rs + (size_t)b * 5 * Nn;
    const int*    reb = g_re + (size_t)b * 5 * Nn;
    const int*    ancb = g_janc + (size_t)b * 5 * Nn;
    const float4* jmb = g_jm + (size_t)b * 5 * Nn;
    const float*  jmbS = reinterpret_cast<const float*>(jmb) + g;

    // factor passes: (I+W^sT) for s=1,2,4,8 (slots 0..3), ping-pong A->B->A->B->A
    if (!norm) {
        factor_pass<false>(A, Bf, rsb + 0 * Nn, reb + 0 * Nn, jmbS + 0 * Nn * 4, 0, tid);
        factor_pass<false>(Bf, A, rsb + 1 * Nn, reb + 1 * Nn, jmbS + 1 * Nn * 4, 0, tid);
        factor_pass<false>(A, Bf, rsb + 2 * Nn, reb + 2 * Nn, jmbS + 2 * Nn * 4, 0, tid);
        factor_pass<false>(Bf, A, rsb + 3 * Nn, reb + 3 * Nn, jmbS + 3 * Nn * 4, 0, tid);
    } else {
        factor_pass<true>(A, Bf, rsb + 0 * Nn, reb + 0 * Nn, 0, jmb + 0 * Nn, tid);
        factor_pass<true>(Bf, A, rsb + 1 * Nn, reb + 1 * Nn, 0, jmb + 1 * Nn, tid);
        factor_pass<true>(A, Bf, rsb + 2 * Nn, reb + 2 * Nn, 0, jmb + 2 * Nn, tid);
        factor_pass<true>(Bf, A, rsb + 3 * Nn, reb + 3 * Nn, 0, jmb + 3 * Nn, tid);
    }

    // stride-16 solve (I - W^16T)^-1, deep -> shallow, in place on A
    {
        const int* rs4 = rsb + 4 * Nn;
        const int* re4 = reb + 4 * Nn;
        const float* m16S = jmbS + 4 * Nn * 4;
        const float4* m164 = jmb + 4 * Nn;
        for (int blk = nb16 - 1; blk >= 0; --blk) {
            int s0 = sls16[blk], e0 = sls16[blk + 1];
            for (int k = s0 + tid; k < e0; k += 256) {
                float4 acc = A[k];
                int lo = __ldg(&rs4[k]), hi = __ldg(&re4[k]);
                for (int j = lo; j < hi; ++j) {
                    float4 x = A[j];
                    if (!norm) {
                        float m = __ldg(&m16S[j * 4]);
                        acc.x += m * x.x; acc.y += m * x.y;
                        acc.z += m * x.z; acc.w += m * x.w;
                    } else {
                        float4 m = __ldg(&m164[j]);
                        acc.x += m.x * x.x; acc.y += m.y * x.y;
                        acc.z += m.z * x.z; acc.w += m.w * x.w;
                    }
                }
                A[k] = acc;
            }
            __syncthreads();
        }
    }

    // c1 = (1 - w^2) * agg   (in place on A)
    {
        const float* w0S = jmbS;             // slot 0 multipliers = wx
        const float4* w04 = jmb;
        for (int k = tid; k < Nn; k += 256) {
            float4 v = A[k];
            if (!norm) {
                float w = __ldg(&w0S[k * 4]);
                float f = 1.f - w * w;
                v.x *= f; v.y *= f; v.z *= f; v.w *= f;
            } else {
                float4 w = __ldg(&w04[k]);
                v.x *= 1.f - w.x * w.x; v.y *= 1.f - w.y * w.y;
                v.z *= 1.f - w.z * w.z; v.w *= 1.f - w.w * w.w;
            }
            A[k] = v;
        }
        __syncthreads();
    }

    // compose c: c2 (slot0), c4 (slot1), c8 (slot2), c16 (slot3); A->B->A->B->A
    if (!norm) {
        compose_pass<false>(A, Bf, ancb + 0 * Nn, jmbS + 0 * Nn * 4, 0, tid);
        compose_pass<false>(Bf, A, ancb + 1 * Nn, jmbS + 1 * Nn * 4, 0, tid);
        compose_pass<false>(A, Bf, ancb + 2 * Nn, jmbS + 2 * Nn * 4, 0, tid);
        compose_pass<false>(Bf, A, ancb + 3 * Nn, jmbS + 3 * Nn * 4, 0, tid);
    } else {
        compose_pass<true>(A, Bf, ancb + 0 * Nn, 0, jmb + 0 * Nn, tid);
        compose_pass<true>(Bf, A, ancb + 1 * Nn, 0, jmb + 1 * Nn, tid);
        compose_pass<true>(A, Bf, ancb + 2 * Nn, 0, jmb + 2 * Nn, tid);
        compose_pass<true>(Bf, A, ancb + 3 * Nn, 0, jmb + 3 * Nn, tid);
    }

    // write c16 to global chunked buffer
    float4* cc = g_cC + ((size_t)b * NCH + ci) * Nn;
    for (int k = tid; k < Nn; k += 256) cc[k] = A[k];
}

// ---------------- K5: strided down-sweep (16 levels per phase), CH=4 ----------------
__global__ __launch_bounds__(256, 2) void k_down() {
    extern __shared__ float4 Z[];
    __shared__ int sls16[404];
    __shared__ int s_nlvl;
    int ci = blockIdx.x, b = blockIdx.y;
    int tid = threadIdx.x;
    bool norm = (ci == 64);
    int g = norm ? 0 : (ci >> 4);

    if (tid == 0) s_nlvl = g_nlvl[b];
    __syncthreads();
    int nlvl = s_nlvl;
    int nph = (nlvl + 15) / 16;
    const int* gls = g_ls + b * (Nn + 2);
    for (int i = tid; i <= nph; i += 256) {
        int lev = 16 * i;
        sls16[i] = (lev == 0) ? 0 : ((lev >= nlvl) ? Nn : gls[lev]);
    }
    __syncthreads();

    float4* cc = g_cC + ((size_t)b * NCH + ci) * Nn;
    const int* aa = g_janc + ((size_t)b * 5 + 4) * Nn;
    const float4* m4 = g_jm + ((size_t)b * 5 + 4) * Nn;
    const float* mS = reinterpret_cast<const float*>(m4) + g;

    for (int t = 0; t < nph; ++t) {
        int s0 = sls16[t], e0 = sls16[t + 1];
        for (int k = s0 + tid; k < e0; k += 256) {
            float4 cv = __ldg(&cc[k]);
            if (t > 0) {
                int a = __ldg(&aa[k]);
                float4 zp = Z[a];
                if (!norm) {
                    float m = __ldg(&mS[k * 4]);
                    cv.x += m * zp.x; cv.y += m * zp.y;
                    cv.z += m * zp.z; cv.w += m * zp.w;
                } else {
                    float4 m = __ldg(&m4[k]);
                    cv.x += m.x * zp.x; cv.y += m.y * zp.y;
                    cv.z += m.z * zp.z; cv.w += m.w * zp.w;
                }
            }
            Z[k] = cv;
        }
        __syncthreads();
    }
    for (int k = tid; k < Nn; k += 256) cc[k] = Z[k];
}

// ---------------- K6: normalize + un-permute + residual ----------------
__global__ __launch_bounds__(256) void k_final(const float* __restrict__ feat,
                                               const float* __restrict__ gammap,
                                               float* __restrict__ out) {
    __shared__ float tile[32 * 65 * 4];
    __shared__ int kq[32];
    int b = blockIdx.y, n0 = blockIdx.x * 32;
    int tid = threadIdx.x;
    if (tid < 32) kq[tid] = g_inv[b * Nn + n0 + tid];
    __syncthreads();
    float4* tile4 = reinterpret_cast<float4*>(tile);
    for (int i = tid; i < 32 * 65; i += 256) {
        int r = i / 65, ci = i - r * 65;
        tile4[i] = g_cC[((size_t)b * NCH + ci) * Nn + kq[r]];
    }
    __syncthreads();
    float gamma = gammap[0];
    int nl = tid & 31;
    int cg = tid >> 5;
    for (int c = cg; c < 256; c += 8) {
        int gr = c >> 6, j = c & 63;
        float filt = tile[(nl * 65 + gr * 16 + (j >> 2)) * 4 + (j & 3)];
        float nrm  = tile[(nl * 65 + 64) * 4 + gr];
        float res = filt / (EPSV + nrm);
        size_t idx = ((size_t)b * CIN + c) * Nn + n0 + nl;
        out[idx] = fmaf(gamma, res, feat[idx]);
    }
}

// ---------------- launcher ----------------
extern "C" void kernel_launch(void* const* d_in, const int* in_sizes, int n_in,
                              void* d_out, int out_size) {
    const float* feature = (const float*)d_in[0];
    const float* guide   = (const float*)d_in[1];
    const float* We      = (const float*)d_in[2];
    const float* Wc      = (const float*)d_in[3];
    const float* Wg      = (const float*)d_in[4];
    const float* beta    = (const float*)d_in[5];
    const float* gamma   = (const float*)d_in[6];
    const int*   order   = (const int*)d_in[7];
    const int*   parent  = (const int*)d_in[8];
    float* out = (float*)d_out;

    cudaFuncSetAttribute(k_pretab, cudaFuncAttributeMaxDynamicSharedMemorySize, 4 * Nn * 4);
    cudaFuncSetAttribute(k_up,     cudaFuncAttributeMaxDynamicSharedMemorySize, 2 * Nn * 16);
    cudaFuncSetAttribute(k_down,   cudaFuncAttributeMaxDynamicSharedMemorySize, Nn * 16);

    // order chosen so k_up is this module's 4th launch (ncu -s 5 profiles it)
    k_gemm<<<dim3(Nn / 128, Bn, 2), 256>>>(feature, guide, We, Wc, Wg);
    k_w<<<dim3(Nn * 2 / 256, Bn), 256>>>(order, parent, beta);
    k_pretab<<<6408, 256, 4 * Nn * 4>>>(feature, order, parent);
    k_up<<<dim3(NCH, Bn), 256, 2 * Nn * 16>>>(order);
    k_down<<<dim3(NCH, Bn), 256, Nn * 16>>>();
    k_final<<<dim3(Nn / 32, Bn), 256>>>(feature, gamma, out);
}

// round 8
// speedup vs baseline: 3.0820x; 1.3426x over previous
#include <cuda_runtime.h>
#include <math.h>

#define Bn   4
#define CIN  256
#define CE   64
#define Gn   4
#define Hn   80
#define Wn   80
#define Nn   (Hn*Wn)        // 6400
#define NCH  65             // channel chunks of 4 (16 per group + 1 norm chunk)
#define EPSV 1e-8f
#define TU   512            // threads for k_up / k_down
#define QU   13             // ceil(Nn/TU)

// ---------------- static device scratch ----------------
__device__ float  g_ft   [Bn*Nn*CIN];     // feature transposed (b, n, c)
__device__ float  g_embt [Bn*Nn*CE];
__device__ float  g_gembt[Bn*Nn*CE];
__device__ float  g_conf [Bn*Nn*Gn];      // (b, n, g) float4-readable
__device__ float  g_w    [Bn*Gn*Nn];      // (b, g, k) BFS order
__device__ float4 g_cC   [Bn*NCH*Nn];     // chunked scan data [b][chunk][k] (4 ch)
__device__ float4 g_jm4  [Bn*5*Nn];       // multipliers float4 [b][slot][k]   (norm chunk)
__device__ float  g_jmP  [Bn*5*Gn*Nn];    // multipliers planar [b][slot][g][k] (scalar chunks)
__device__ int    g_janc [Bn*5*Nn];       // ancestors   [b][slot][k]
__device__ int    g_rs   [Bn*5*Nn];       // descendant-range start [b][slot][k]
__device__ int    g_re   [Bn*5*Nn];       // descendant-range end
__device__ int    g_inv  [Bn*Nn];
__device__ int    g_ls   [Bn*(Nn+2)];
__device__ int    g_nlvl [Bn];

// ---------------- packed f32x2 FMA ----------------
__device__ __forceinline__ void ffma2(unsigned long long &d,
                                      unsigned long long a,
                                      unsigned long long b) {
    asm("fma.rn.f32x2 %0, %1, %2, %0;" : "+l"(d) : "l"(a), "l"(b));
}

// ---------------- K1: skinny GEMMs via packed f32x2 FMA ----------------
__global__ __launch_bounds__(256) void k_gemm(const float* __restrict__ feat,
                                              const float* __restrict__ guide,
                                              const float* __restrict__ We,
                                              const float* __restrict__ Wc,
                                              const float* __restrict__ Wg) {
    __shared__ char smraw[34816];
    float*  xs = reinterpret_cast<float*>(smraw);
    float2* ws = reinterpret_cast<float2*>(smraw + 16384);
    float*  stage = reinterpret_cast<float*>(smraw);

    int tid = threadIdx.x;
    int os = tid >> 5;
    int nq = tid & 31;
    int n0 = blockIdx.x * 128;
    int b  = blockIdx.y;
    int path = blockIdx.z;

    const float* X = (path == 0 ? feat : guide) + (size_t)b * CIN * Nn;

    unsigned long long acc[9][2];
#pragma unroll
    for (int j = 0; j < 9; ++j) { acc[j][0] = 0ull; acc[j][1] = 0ull; }

    for (int kc = 0; kc < 256; kc += 32) {
        const float* Xb = X + (size_t)kc * Nn + n0;
#pragma unroll
        for (int i = tid; i < 1024; i += 256) {
            int kk = i >> 5, c4 = i & 31;
            *reinterpret_cast<float4*>(&xs[kk * 128 + c4 * 4]) =
                *reinterpret_cast<const float4*>(&Xb[(size_t)kk * Nn + c4 * 4]);
        }
#pragma unroll
        for (int i = tid; i < 2304; i += 256) {
            int o = i >> 5, kk = i & 31;
            float v = 0.f;
            if (path == 0) {
                if (o < 64)       v = We[o * 256 + kc + kk];
                else if (o < 68)  v = Wc[(o - 64) * 256 + kc + kk];
            } else {
                if (o < 64)       v = Wg[o * 256 + kc + kk];
            }
            ws[i] = make_float2(v, v);
        }
        __syncthreads();
#pragma unroll 2
        for (int kk = 0; kk < 32; ++kk) {
            float4 x4 = *reinterpret_cast<const float4*>(&xs[kk * 128 + nq * 4]);
            unsigned long long xlo = *reinterpret_cast<unsigned long long*>(&x4.x);
            unsigned long long xhi = *reinterpret_cast<unsigned long long*>(&x4.z);
#pragma unroll
            for (int j = 0; j < 9; ++j) {
                float2 wv = ws[(os * 9 + j) * 32 + kk];
                unsigned long long wp = *reinterpret_cast<unsigned long long*>(&wv);
                ffma2(acc[j][0], xlo, wp);
                ffma2(acc[j][1], xhi, wp);
            }
        }
        __syncthreads();
    }
#pragma unroll
    for (int j = 0; j < 9; ++j) {
        int o = os * 9 + j;
        if (o < 68) {
            float2 lo = *reinterpret_cast<float2*>(&acc[j][0]);
            float2 hi = *reinterpret_cast<float2*>(&acc[j][1]);
            stage[(nq * 4 + 0) * 68 + o] = lo.x;
            stage[(nq * 4 + 1) * 68 + o] = lo.y;
            stage[(nq * 4 + 2) * 68 + o] = hi.x;
            stage[(nq * 4 + 3) * 68 + o] = hi.y;
        }
    }
    __syncthreads();
    float* outt = (path == 0) ? g_embt : g_gembt;
#pragma unroll
    for (int i = tid; i < 2048; i += 256) {
        int n = i >> 4, c4 = i & 15;
        float4 v = *reinterpret_cast<float4*>(&stage[n * 68 + c4 * 4]);
        *reinterpret_cast<float4*>(&outt[((size_t)b * Nn + n0 + n) * 64 + c4 * 4]) = v;
    }
    if (path == 0) {
#pragma unroll
        for (int i = tid; i < 512; i += 256) {
            int n = i >> 2, gg = i & 3;
            float x = stage[n * 68 + 64 + gg];
            g_conf[((size_t)b * Nn + n0 + n) * 4 + gg] = 1.f / (1.f + expf(-x));
        }
    }
}

// ---------------- K2: edge weights, 2 threads per node ----------------
__global__ __launch_bounds__(256) void k_w(const int* __restrict__ order,
                                           const int* __restrict__ parent,
                                           const float* __restrict__ beta) {
    int b = blockIdx.y;
    int idx = blockIdx.x * 256 + threadIdx.x;
    int k = idx >> 1, half = idx & 1;
    if (k >= Nn) return;
    int n1 = order[b * Nn + k];
    int p  = parent[b * Nn + k];
    int n0 = order[b * Nn + p];
    int coff = half * 32;
    const float4* e1 = reinterpret_cast<const float4*>(g_embt  + ((size_t)b * Nn + n1) * 64 + coff);
    const float4* e0 = reinterpret_cast<const float4*>(g_embt  + ((size_t)b * Nn + n0) * 64 + coff);
    const float4* q1 = reinterpret_cast<const float4*>(g_gembt + ((size_t)b * Nn + n1) * 64 + coff);
    const float4* q0 = reinterpret_cast<const float4*>(g_gembt + ((size_t)b * Nn + n0) * 64 + coff);
    float d[2] = {0.f, 0.f};
#pragma unroll
    for (int i = 0; i < 8; ++i) {
        float4 a = e1[i], c = e0[i];
        float dx = a.x - c.x, dy = a.y - c.y, dz = a.z - c.z, dw = a.w - c.w;
        d[i >> 2] += dx * dx + dy * dy + dz * dz + dw * dw;
    }
#pragma unroll
    for (int i = 0; i < 8; ++i) {
        float4 a = q1[i], c = q0[i];
        float dx = a.x - c.x, dy = a.y - c.y, dz = a.z - c.z, dw = a.w - c.w;
        d[i >> 2] += dx * dx + dy * dy + dz * dz + dw * dw;
    }
#pragma unroll
    for (int j = 0; j < 2; ++j) {
        int g = half * 2 + j;
        float bb = beta[g];
        g_w[((size_t)b * 4 + g) * Nn + k] = expf(-(d[j] + bb * bb));
    }
}

// ---------------- K3: fused transpose + levels + jump tables/ranges ----------------
__global__ __launch_bounds__(256) void k_pretab(const float* __restrict__ feat,
                                                const int* __restrict__ order,
                                                const int* __restrict__ parent) {
    extern __shared__ int sh[];
    int bid = blockIdx.x;
    int tid = threadIdx.x;

    if (bid < 6400) {
        // -------- transpose role --------
        __shared__ float t[32][33];
        int b = bid / 1600;
        int r2 = bid - b * 1600;
        int c0 = (r2 / 200) * 32;
        int n0 = (r2 % 200) * 32;
        int tx = tid & 31, ty = tid >> 5;   // 32 x 8
        const float* src = feat + ((size_t)b * CIN + c0) * Nn + n0;
#pragma unroll
        for (int r = 0; r < 32; r += 8)
            t[ty + r][tx] = src[(size_t)(ty + r) * Nn + tx];
        __syncthreads();
        float* dst = g_ft + ((size_t)b * Nn + n0) * CIN + c0;
#pragma unroll
        for (int r = 0; r < 32; r += 8)
            dst[(size_t)(ty + r) * CIN + tx] = t[tx][ty + r];
        return;
    }

    if (bid < 6404) {
        // -------- levels role --------
        int* a0 = sh;
        int* a1 = sh + Nn;
        int* l0 = sh + 2 * Nn;
        int* l1 = sh + 3 * Nn;
        __shared__ int s_more;
        int b = bid - 6400;
        const int* pp = parent + b * Nn;
        const int* od = order + b * Nn;
        for (int k = tid; k < Nn; k += 256) {
            a0[k] = pp[k];
            l0[k] = (k == 0) ? 0 : 1;
            g_inv[b * Nn + od[k]] = k;
        }
        __syncthreads();
        int* aa = a0; int* ab = a1; int* la = l0; int* lb = l1;
        for (int it = 0; it < 13; ++it) {
            if (tid == 0) s_more = 0;
            __syncthreads();
            int any = 0;
            for (int k = tid; k < Nn; k += 256) {
                int a = aa[k];
                lb[k] = la[k] + la[a];
                int na = aa[a];
                ab[k] = na;
                any |= na;
            }
            if (any) s_more = 1;
            __syncthreads();
            int* tmp = aa; aa = ab; ab = tmp;
            tmp = la; la = lb; lb = tmp;
            if (!s_more) break;
        }
        int* ls = g_ls + b * (Nn + 2);
        for (int k = tid; k < Nn; k += 256) {
            if (k == 0) ls[0] = 0;
            else if (la[k] != la[k - 1]) ls[la[k]] = k;
            if (k == Nn - 1) { g_nlvl[b] = la[k] + 1; ls[la[k] + 1] = Nn; }
        }
        return;
    }

    // -------- tables role --------
    {
        int b = bid - 6404;
        const int* pp = parent + b * Nn;
        int*    anc = g_janc + (size_t)b * 5 * Nn;
        float4* jm4 = g_jm4  + (size_t)b * 5 * Nn;
        for (int k = tid; k < Nn; k += 256) {
            anc[k] = pp[k];
            float4 mv;
            mv.x = (k == 0) ? 0.f : g_w[((size_t)b * 4 + 0) * Nn + k];
            mv.y = (k == 0) ? 0.f : g_w[((size_t)b * 4 + 1) * Nn + k];
            mv.z = (k == 0) ? 0.f : g_w[((size_t)b * 4 + 2) * Nn + k];
            mv.w = (k == 0) ? 0.f : g_w[((size_t)b * 4 + 3) * Nn + k];
            jm4[k] = mv;
        }
        __syncthreads();
        for (int s = 1; s < 5; ++s) {
            for (int k = tid; k < Nn; k += 256) {
                int a = anc[(s - 1) * Nn + k];
                anc[s * Nn + k] = anc[(s - 1) * Nn + a];
                float4 mk = jm4[(s - 1) * Nn + k];
                float4 ma = jm4[(s - 1) * Nn + a];
                float4 mo;
                mo.x = mk.x * ma.x; mo.y = mk.y * ma.y;
                mo.z = mk.z * ma.z; mo.w = mk.w * ma.w;
                jm4[s * Nn + k] = mo;
            }
            __syncthreads();
        }
        // planar copy for scalar chunks
        float* jmP = g_jmP + (size_t)b * 5 * Gn * Nn;
        for (int s = 0; s < 5; ++s) {
            for (int k = tid; k < Nn; k += 256) {
                float4 m = jm4[s * Nn + k];
                jmP[(s * Gn + 0) * Nn + k] = m.x;
                jmP[(s * Gn + 1) * Nn + k] = m.y;
                jmP[(s * Gn + 2) * Nn + k] = m.z;
                jmP[(s * Gn + 3) * Nn + k] = m.w;
            }
        }
        // ranges
        int* rs = g_rs + (size_t)b * 5 * Nn;
        int* re = g_re + (size_t)b * 5 * Nn;
        for (int i = tid; i < 5 * Nn; i += 256) { rs[i] = 0; re[i] = 0; }
        __syncthreads();
        for (int s = 0; s < 5; ++s) {
            const int* as = anc + s * Nn;
            for (int j = tid; j < Nn; j += 256) {
                int a = as[j];
                int ap = (j > 0) ? as[j - 1] : -1;
                if (a != ap) {
                    rs[s * Nn + a] = j;
                    if (j > 0) re[s * Nn + ap] = j;
                }
                if (j == Nn - 1) re[s * Nn + a] = Nn;
            }
        }
    }
}

// ---------------- K4: up-sweep, atomic-free gathers, 512 threads, prefetched ----------------
template<bool NORM>
__device__ __forceinline__ void factor_pass(const float4* __restrict__ in,
                                            float4* __restrict__ out,
                                            const int* __restrict__ rs,
                                            const int* __restrict__ re,
                                            const float* __restrict__ mP,
                                            const float4* __restrict__ m4,
                                            int tid) {
    int lo[QU], hi[QU];
#pragma unroll
    for (int q = 0; q < QU; ++q) {
        int k = tid + TU * q;
        if (k < Nn) { lo[q] = __ldg(&rs[k]); hi[q] = __ldg(&re[k]); }
        else        { lo[q] = 0; hi[q] = 0; }
    }
#pragma unroll
    for (int q = 0; q < QU; ++q) {
        int k = tid + TU * q;
        if (k < Nn) {
            float4 acc = in[k];
            for (int j = lo[q]; j < hi[q]; ++j) {
                float4 x = in[j];
                if (NORM) {
                    float4 m = __ldg(&m4[j]);
                    acc.x += m.x * x.x; acc.y += m.y * x.y;
                    acc.z += m.z * x.z; acc.w += m.w * x.w;
                } else {
                    float m = __ldg(&mP[j]);
                    acc.x += m * x.x; acc.y += m * x.y;
                    acc.z += m * x.z; acc.w += m * x.w;
                }
            }
            out[k] = acc;
        }
    }
    __syncthreads();
}

template<bool NORM>
__device__ __forceinline__ void compose_pass(const float4* __restrict__ in,
                                             float4* __restrict__ out,
                                             const int* __restrict__ anc,
                                             const float* __restrict__ mP,
                                             const float4* __restrict__ m4,
                                             int tid) {
    int av[QU];
    float ms[QU];
    float4 mv[QU];
#pragma unroll
    for (int q = 0; q < QU; ++q) {
        int k = tid + TU * q;
        if (k < Nn) {
            av[q] = __ldg(&anc[k]);
            if (NORM) mv[q] = __ldg(&m4[k]);
            else      ms[q] = __ldg(&mP[k]);
        } else av[q] = 0;
    }
#pragma unroll
    for (int q = 0; q < QU; ++q) {
        int k = tid + TU * q;
        if (k < Nn) {
            float4 ck = in[k];
            float4 ca = in[av[q]];
            if (NORM) {
                ck.x += mv[q].x * ca.x; ck.y += mv[q].y * ca.y;
                ck.z += mv[q].z * ca.z; ck.w += mv[q].w * ca.w;
            } else {
                float m = ms[q];
                ck.x += m * ca.x; ck.y += m * ca.y;
                ck.z += m * ca.z; ck.w += m * ca.w;
            }
            out[k] = ck;
        }
    }
    __syncthreads();
}

__global__ __launch_bounds__(TU, 1) void k_up(const int* __restrict__ order) {
    extern __shared__ float4 sm4[];
    float4* A = sm4;
    float4* Bf = sm4 + Nn;
    __shared__ int sls16[404];
    __shared__ int s_nlvl;
    int ci = blockIdx.x, b = blockIdx.y;
    int tid = threadIdx.x;
    bool norm = (ci == 64);
    int g = norm ? 0 : (ci >> 4);
    int q = ci & 15;

    if (tid == 0) s_nlvl = g_nlvl[b];
    __syncthreads();
    int nlvl = s_nlvl;
    int nb16 = (nlvl + 15) / 16;
    const int* gls = g_ls + b * (Nn + 2);
    for (int i = tid; i <= nb16; i += TU) {
        int lev = 16 * i;
        sls16[i] = (lev == 0) ? 0 : ((lev >= nlvl) ? Nn : gls[lev]);
    }

    // init
    const int* od = order + b * Nn;
    if (!norm) {
        int ftcol = g * 64 + q * 4;
        for (int k = tid; k < Nn; k += TU) {
            int n = od[k];
            float cf = g_conf[((size_t)b * Nn + n) * 4 + g];
            float4 v = *reinterpret_cast<const float4*>(g_ft + ((size_t)b * Nn + n) * CIN + ftcol);
            v.x *= cf; v.y *= cf; v.z *= cf; v.w *= cf;
            A[k] = v;
        }
    } else {
        for (int k = tid; k < Nn; k += TU) {
            int n = od[k];
            A[k] = *reinterpret_cast<const float4*>(g_conf + ((size_t)b * Nn + n) * 4);
        }
    }
    __syncthreads();

    const int*    rsb  = g_rs   + (size_t)b * 5 * Nn;
    const int*    reb  = g_re   + (size_t)b * 5 * Nn;
    const int*    ancb = g_janc + (size_t)b * 5 * Nn;
    const float4* m4b  = g_jm4  + (size_t)b * 5 * Nn;
    const float*  mPb  = g_jmP  + (size_t)b * 5 * Gn * Nn + (size_t)g * Nn;

    // factor passes: (I+W^sT), s=1,2,4,8
    if (!norm) {
        factor_pass<false>(A, Bf, rsb, reb, mPb, 0, tid);
        factor_pass<false>(Bf, A, rsb + Nn, reb + Nn, mPb + Gn * Nn, 0, tid);
        factor_pass<false>(A, Bf, rsb + 2 * Nn, reb + 2 * Nn, mPb + 2 * Gn * Nn, 0, tid);
        factor_pass<false>(Bf, A, rsb + 3 * Nn, reb + 3 * Nn, mPb + 3 * Gn * Nn, 0, tid);
    } else {
        factor_pass<true>(A, Bf, rsb, reb, 0, m4b, tid);
        factor_pass<true>(Bf, A, rsb + Nn, reb + Nn, 0, m4b + Nn, tid);
        factor_pass<true>(A, Bf, rsb + 2 * Nn, reb + 2 * Nn, 0, m4b + 2 * Nn, tid);
        factor_pass<true>(Bf, A, rsb + 3 * Nn, reb + 3 * Nn, 0, m4b + 3 * Nn, tid);
    }

    // stride-16 solve (I - W^16T)^-1, deep -> shallow, in place on A
    {
        const int* rs4 = rsb + 4 * Nn;
        const int* re4 = reb + 4 * Nn;
        const float* m16P = mPb + 4 * Gn * Nn;
        const float4* m164 = m4b + 4 * Nn;
        for (int blk = nb16 - 1; blk >= 0; --blk) {
            int s0 = sls16[blk], e0 = sls16[blk + 1];
            for (int k = s0 + tid; k < e0; k += TU) {
                float4 acc = A[k];
                int lo = __ldg(&rs4[k]), hi = __ldg(&re4[k]);
                for (int j = lo; j < hi; ++j) {
                    float4 x = A[j];
                    if (!norm) {
                        float m = __ldg(&m16P[j]);
                        acc.x += m * x.x; acc.y += m * x.y;
                        acc.z += m * x.z; acc.w += m * x.w;
                    } else {
                        float4 m = __ldg(&m164[j]);
                        acc.x += m.x * x.x; acc.y += m.y * x.y;
                        acc.z += m.z * x.z; acc.w += m.w * x.w;
                    }
                }
                A[k] = acc;
            }
            __syncthreads();
        }
    }

    // c1 = (1 - w^2) * agg
    {
        for (int k = tid; k < Nn; k += TU) {
            float4 v = A[k];
            if (!norm) {
                float w = __ldg(&mPb[k]);
                float f = 1.f - w * w;
                v.x *= f; v.y *= f; v.z *= f; v.w *= f;
            } else {
                float4 w = __ldg(&m4b[k]);
                v.x *= 1.f - w.x * w.x; v.y *= 1.f - w.y * w.y;
                v.z *= 1.f - w.z * w.z; v.w *= 1.f - w.w * w.w;
            }
            A[k] = v;
        }
        __syncthreads();
    }

    // compose c: slots 0..3
    if (!norm) {
        compose_pass<false>(A, Bf, ancb, mPb, 0, tid);
        compose_pass<false>(Bf, A, ancb + Nn, mPb + Gn * Nn, 0, tid);
        compose_pass<false>(A, Bf, ancb + 2 * Nn, mPb + 2 * Gn * Nn, 0, tid);
        compose_pass<false>(Bf, A, ancb + 3 * Nn, mPb + 3 * Gn * Nn, 0, tid);
    } else {
        compose_pass<true>(A, Bf, ancb, 0, m4b, tid);
        compose_pass<true>(Bf, A, ancb + Nn, 0, m4b + Nn, tid);
        compose_pass<true>(A, Bf, ancb + 2 * Nn, 0, m4b + 2 * Nn, tid);
        compose_pass<true>(Bf, A, ancb + 3 * Nn, 0, m4b + 3 * Nn, tid);
    }

    float4* cc = g_cC + ((size_t)b * NCH + ci) * Nn;
    for (int k = tid; k < Nn; k += TU) cc[k] = A[k];
}

// ---------------- K5: strided down-sweep (16 levels per phase) ----------------
__global__ __launch_bounds__(TU, 2) void k_down() {
    extern __shared__ float4 Z[];
    __shared__ int sls16[404];
    __shared__ int s_nlvl;
    int ci = blockIdx.x, b = blockIdx.y;
    int tid = threadIdx.x;
    bool norm = (ci == 64);
    int g = norm ? 0 : (ci >> 4);

    if (tid == 0) s_nlvl = g_nlvl[b];
    __syncthreads();
    int nlvl = s_nlvl;
    int nph = (nlvl + 15) / 16;
    const int* gls = g_ls + b * (Nn + 2);
    for (int i = tid; i <= nph; i += TU) {
        int lev = 16 * i;
        sls16[i] = (lev == 0) ? 0 : ((lev >= nlvl) ? Nn : gls[lev]);
    }
    __syncthreads();

    float4* cc = g_cC + ((size_t)b * NCH + ci) * Nn;
    const int* aa = g_janc + ((size_t)b * 5 + 4) * Nn;
    const float4* m4 = g_jm4 + ((size_t)b * 5 + 4) * Nn;
    const float* mP = g_jmP + (size_t)b * 5 * Gn * Nn + (size_t)(4 * Gn + g) * Nn;

    for (int t = 0; t < nph; ++t) {
        int s0 = sls16[t], e0 = sls16[t + 1];
        for (int k = s0 + tid; k < e0; k += TU) {
            float4 cv = __ldg(&cc[k]);
            if (t > 0) {
                int a = __ldg(&aa[k]);
                float4 zp = Z[a];
                if (!norm) {
                    float m = __ldg(&mP[k]);
                    cv.x += m * zp.x; cv.y += m * zp.y;
                    cv.z += m * zp.z; cv.w += m * zp.w;
                } else {
                    float4 m = __ldg(&m4[k]);
                    cv.x += m.x * zp.x; cv.y += m.y * zp.y;
                    cv.z += m.z * zp.z; cv.w += m.w * zp.w;
                }
            }
            Z[k] = cv;
        }
        __syncthreads();
    }
    for (int k = tid; k < Nn; k += TU) cc[k] = Z[k];
}

// ---------------- K6: normalize + un-permute + residual ----------------
__global__ __launch_bounds__(256) void k_final(const float* __restrict__ feat,
                                               const float* __restrict__ gammap,
                                               float* __restrict__ out) {
    __shared__ float tile[32 * 65 * 4];
    __shared__ int kq[32];
    int b = blockIdx.y, n0 = blockIdx.x * 32;
    int tid = threadIdx.x;
    if (tid < 32) kq[tid] = g_inv[b * Nn + n0 + tid];
    __syncthreads();
    float4* tile4 = reinterpret_cast<float4*>(tile);
    for (int i = tid; i < 32 * 65; i += 256) {
        int r = i / 65, ci = i - r * 65;
        tile4[i] = g_cC[((size_t)b * NCH + ci) * Nn + kq[r]];
    }
    __syncthreads();
    float gamma = gammap[0];
    int nl = tid & 31;
    int cg = tid >> 5;
    for (int c = cg; c < 256; c += 8) {
        int gr = c >> 6, j = c & 63;
        float filt = tile[(nl * 65 + gr * 16 + (j >> 2)) * 4 + (j & 3)];
        float nrm  = tile[(nl * 65 + 64) * 4 + gr];
        float res = filt / (EPSV + nrm);
        size_t idx = ((size_t)b * CIN + c) * Nn + n0 + nl;
        out[idx] = fmaf(gamma, res, feat[idx]);
    }
}

// ---------------- launcher ----------------
extern "C" void kernel_launch(void* const* d_in, const int* in_sizes, int n_in,
                              void* d_out, int out_size) {
    const float* feature = (const float*)d_in[0];
    const float* guide   = (const float*)d_in[1];
    const float* We      = (const float*)d_in[2];
    const float* Wc      = (const float*)d_in[3];
    const float* Wg      = (const float*)d_in[4];
    const float* beta    = (const float*)d_in[5];
    const float* gamma   = (const float*)d_in[6];
    const int*   order   = (const int*)d_in[7];
    const int*   parent  = (const int*)d_in[8];
    float* out = (float*)d_out;

    cudaFuncSetAttribute(k_pretab, cudaFuncAttributeMaxDynamicSharedMemorySize, 4 * Nn * 4);
    cudaFuncSetAttribute(k_up,     cudaFuncAttributeMaxDynamicSharedMemorySize, 2 * Nn * 16);
    cudaFuncSetAttribute(k_down,   cudaFuncAttributeMaxDynamicSharedMemorySize, Nn * 16);

    // k_up is this module's 4th launch (ncu -s 5 profiles it)
    k_gemm<<<dim3(Nn / 128, Bn, 2), 256>>>(feature, guide, We, Wc, Wg);
    k_w<<<dim3(Nn * 2 / 256, Bn), 256>>>(order, parent, beta);
    k_pretab<<<6408, 256, 4 * Nn * 4>>>(feature, order, parent);
    k_up<<<dim3(NCH, Bn), TU, 2 * Nn * 16>>>(order);
    k_down<<<dim3(NCH, Bn), TU, Nn * 16>>>();
    k_final<<<dim3(Nn / 32, Bn), 256>>>(feature, gamma, out);
}